// round 9
// baseline (speedup 1.0000x reference)
#include <cuda_runtime.h>
#include <cuda_bf16.h>
#include <math.h>
#include <stdint.h>

// Problem constants
#define Bsz 16
#define CIn 32
#define COn 32
#define Hn  256
#define Wn  256
#define KM  32
#define SXn 64
#define RTOT (Bsz*CIn*Hn)   // 131072 rows

// ============================ fragment-ordered constant tables ============================
// fwdW B frags:  [kc(4)][ks(4)][nt(8)][lane(32)]  uint2 (2 regs), hi & lo planes
__device__ __align__(16) uint2 g_FWBh[4*4*8*32], g_FWBl[4*4*8*32];
// fwdH A frags:  [kc(4)][ks(4)][mt(4)][lane]      uint4 (4 regs), 4 planes (re/im x hi/lo)
__device__ __align__(16) uint4 g_FHArh[4*4*4*32], g_FHArl[4*4*4*32],
                               g_FHAih[4*4*4*32], g_FHAil[4*4*4*32];
// invH A frags:  [hq(4)][ks(4)][mt(4)][lane]      uint4, 4 planes
__device__ __align__(16) uint4 g_IHArh[4*4*4*32], g_IHArl[4*4*4*32],
                               g_IHAih[4*4*4*32], g_IHAil[4*4*4*32];
// irfftW B frags: [nh(2)][ntile(16)][ks(4)][lane] uint2, hi & lo
__device__ __align__(16) uint2 g_IRBh[2*16*4*32], g_IRBl[2*16*4*32];

// ============================ bf16 data planes (producer-emitted) ============================
__device__ __align__(16) __nv_bfloat16 g_XwBh[(size_t)Bsz*CIn*64*256];  // fwdW out -> fwdH B
__device__ __align__(16) __nv_bfloat16 g_XwBl[(size_t)Bsz*CIn*64*256];
__device__ __align__(16) __nv_bfloat16 g_OfBh[(size_t)Bsz*COn*64*64];   // mix out  -> invH B
__device__ __align__(16) __nv_bfloat16 g_OfBl[(size_t)Bsz*COn*64*64];
__device__ __align__(16) __nv_bfloat16 g_TmpAh[(size_t)Bsz*COn*256*64]; // invH out -> irfftW A
__device__ __align__(16) __nv_bfloat16 g_TmpAl[(size_t)Bsz*COn*256*64];

__device__ float2 g_Xf[(size_t)Bsz*CIn*SXn*KM];   // fwdH out [bci][sx][ky] (f32, mix input)
__device__ float2 g_Wt [2*1024*1024];
__device__ float2 g_Wet[2*1024*1024];

// ============================ helpers ============================
__device__ __forceinline__ uint32_t pack_bf(__nv_bfloat16 a, __nv_bfloat16 b) {
    return (uint32_t)__bfloat16_as_ushort(a) | ((uint32_t)__bfloat16_as_ushort(b) << 16);
}
__device__ __forceinline__ void split_bf(float v, __nv_bfloat16& h, __nv_bfloat16& l) {
    h = __float2bfloat16(v);
    l = __float2bfloat16(v - __bfloat162float(h));
}
__device__ __forceinline__ void mma16816(float* c, const uint32_t* a, const uint32_t* b) {
    asm volatile("mma.sync.aligned.m16n8k16.row.col.f32.bf16.bf16.f32 "
        "{%0,%1,%2,%3}, {%4,%5,%6,%7}, {%8,%9}, {%0,%1,%2,%3};"
        : "+f"(c[0]), "+f"(c[1]), "+f"(c[2]), "+f"(c[3])
        : "r"(a[0]), "r"(a[1]), "r"(a[2]), "r"(a[3]), "r"(b[0]), "r"(b[1]));
}

__global__ void k_init() {
    int t = blockIdx.x * blockDim.x + threadIdx.x;
    if (t < 4096) {                       // fwdW B frags
        int lane = t & 31, nt = (t >> 5) & 7, ks = (t >> 8) & 3, kc = t >> 10;
        int g = lane >> 2, t4 = lane & 3;
        int n = nt * 8 + g, q = n >> 1;
        uint32_t hv[2], lv[2];
        #pragma unroll
        for (int reg = 0; reg < 2; reg++) {
            int k0 = kc * 64 + ks * 16 + 2 * t4 + reg * 8;
            __nv_bfloat16 h0, l0, h1, l1;
            float s, c;
            sincospif((float)(q * k0) / 128.0f, &s, &c);
            split_bf((n & 1) ? -s : c, h0, l0);
            sincospif((float)(q * (k0 + 1)) / 128.0f, &s, &c);
            split_bf((n & 1) ? -s : c, h1, l1);
            hv[reg] = pack_bf(h0, h1); lv[reg] = pack_bf(l0, l1);
        }
        g_FWBh[t] = make_uint2(hv[0], hv[1]);
        g_FWBl[t] = make_uint2(lv[0], lv[1]);
    } else if (t < 6144) {                // fwdH A frags
        int e = t - 4096;
        int lane = e & 31, mt = (e >> 5) & 3, ks = (e >> 7) & 3, kc = e >> 9;
        int g = lane >> 2, t4 = lane & 3;
        uint32_t rh[4], rl[4], ih[4], il[4];
        #pragma unroll
        for (int reg = 0; reg < 4; reg++) {
            int sx = mt * 16 + g + (reg & 1) * 8;
            int kx = (sx < 32) ? sx : (192 + sx);
            int h0 = kc * 64 + ks * 16 + 2 * t4 + (reg >> 1) * 8;
            __nv_bfloat16 a, b, c1, d1, a2, b2, c2, d2;
            float s, c;
            sincospif((float)(kx * h0) / 128.0f, &s, &c);
            split_bf(c, a, b); split_bf(-s, c1, d1);
            sincospif((float)(kx * (h0 + 1)) / 128.0f, &s, &c);
            split_bf(c, a2, b2); split_bf(-s, c2, d2);
            rh[reg] = pack_bf(a, a2);  rl[reg] = pack_bf(b, b2);
            ih[reg] = pack_bf(c1, c2); il[reg] = pack_bf(d1, d2);
        }
        g_FHArh[e] = make_uint4(rh[0], rh[1], rh[2], rh[3]);
        g_FHArl[e] = make_uint4(rl[0], rl[1], rl[2], rl[3]);
        g_FHAih[e] = make_uint4(ih[0], ih[1], ih[2], ih[3]);
        g_FHAil[e] = make_uint4(il[0], il[1], il[2], il[3]);
    } else if (t < 8192) {                // invH A frags
        int e = t - 6144;
        int lane = e & 31, mt = (e >> 5) & 3, ks = (e >> 7) & 3, hq = e >> 9;
        int g = lane >> 2, t4 = lane & 3;
        uint32_t rh[4], rl[4], ih[4], il[4];
        #pragma unroll
        for (int reg = 0; reg < 4; reg++) {
            int h = hq * 64 + mt * 16 + g + (reg & 1) * 8;
            int s0 = ks * 16 + 2 * t4 + (reg >> 1) * 8;
            __nv_bfloat16 a, b, c1, d1, a2, b2, c2, d2;
            float s, c;
            int kx0 = (s0 < 32) ? s0 : (192 + s0);
            sincospif((float)(kx0 * h) / 128.0f, &s, &c);
            split_bf(c, a, b); split_bf(s, c1, d1);
            int s1 = s0 + 1;
            int kx1 = (s1 < 32) ? s1 : (192 + s1);
            sincospif((float)(kx1 * h) / 128.0f, &s, &c);
            split_bf(c, a2, b2); split_bf(s, c2, d2);
            rh[reg] = pack_bf(a, a2);  rl[reg] = pack_bf(b, b2);
            ih[reg] = pack_bf(c1, c2); il[reg] = pack_bf(d1, d2);
        }
        g_IHArh[e] = make_uint4(rh[0], rh[1], rh[2], rh[3]);
        g_IHArl[e] = make_uint4(rl[0], rl[1], rl[2], rl[3]);
        g_IHAih[e] = make_uint4(ih[0], ih[1], ih[2], ih[3]);
        g_IHAil[e] = make_uint4(il[0], il[1], il[2], il[3]);
    } else if (t < 12288) {               // irfftW B frags
        int e = t - 8192;
        int lane = e & 31, ks = (e >> 5) & 3, nt = (e >> 7) & 15, nh = e >> 11;
        int g = lane >> 2, t4 = lane & 3;
        int w = nh * 128 + nt * 8 + g;
        uint32_t hv[2], lv[2];
        #pragma unroll
        for (int reg = 0; reg < 2; reg++) {
            int j0 = ks * 16 + 2 * t4 + reg * 8;
            __nv_bfloat16 h0, l0, h1, l1;
            float s, c;
            int q0 = j0 >> 1;
            float al0 = ((q0 == 0) ? 1.0f : 2.0f) * (1.0f / 256.0f);
            sincospif((float)(q0 * w) / 128.0f, &s, &c);
            split_bf((j0 & 1) ? -al0 * s : al0 * c, h0, l0);
            int j1 = j0 + 1, q1 = j1 >> 1;
            float al1 = ((q1 == 0) ? 1.0f : 2.0f) * (1.0f / 256.0f);
            sincospif((float)(q1 * w) / 128.0f, &s, &c);
            split_bf((j1 & 1) ? -al1 * s : al1 * c, h1, l1);
            hv[reg] = pack_bf(h0, h1); lv[reg] = pack_bf(l0, l1);
        }
        g_IRBh[e] = make_uint2(hv[0], hv[1]);
        g_IRBl[e] = make_uint2(lv[0], lv[1]);
    }
}

// ---- K0b: transpose weights [p][kxy] -> [kxy][p] ----
__global__ void __launch_bounds__(256) k_wtrans(const float* __restrict__ w0,
                                                const float* __restrict__ w1,
                                                const float* __restrict__ we0,
                                                const float* __restrict__ we1) {
    __shared__ float2 sm[32][33];
    int bid = blockIdx.x;
    int arr = bid >> 10;
    int tile = bid & 1023;
    int I = tile >> 5, J = tile & 31;
    const float2* src = (const float2*)((arr == 0) ? w0 : (arr == 1) ? w1 : (arr == 2) ? we0 : we1);
    float2* dst = (arr < 2) ? (g_Wt + (size_t)arr * 1024 * 1024)
                            : (g_Wet + (size_t)(arr - 2) * 1024 * 1024);
    int t = threadIdx.x;
    int c = t & 31, rq = t >> 5;
    #pragma unroll
    for (int i = 0; i < 4; i++)
        sm[rq + 8 * i][c] = src[(size_t)(I * 32 + rq + 8 * i) * 1024 + J * 32 + c];
    __syncthreads();
    #pragma unroll
    for (int i = 0; i < 4; i++)
        dst[(size_t)(J * 32 + rq + 8 * i) * 1024 + I * 32 + c] = sm[c][rq + 8 * i];
}

// ============== K1: fwd DFT along W; B frags from global; emits bf16 planes ==============
#define FW_SMEM 36864
__global__ void __launch_bounds__(256) k_fwdW_m(const float* __restrict__ x) {
    extern __shared__ unsigned char smem[];
    __nv_bfloat16* Ah = (__nv_bfloat16*)(smem);
    __nv_bfloat16* Al = (__nv_bfloat16*)(smem + 18432);
    int tid = threadIdx.x, lane = tid & 31, wid = tid >> 5;
    int g = lane >> 2, t4 = lane & 3;
    size_t rowBase = (size_t)blockIdx.x * 128;
    int m0 = wid * 16;
    float acc[8][4];
    #pragma unroll
    for (int nt = 0; nt < 8; nt++)
        #pragma unroll
        for (int i = 0; i < 4; i++) acc[nt][i] = 0.f;

    const float4* xg = (const float4*)x;
    for (int kc = 0; kc < 4; kc++) {
        __syncthreads();
        #pragma unroll
        for (int i = 0; i < 8; i++) {
            int idx = tid + 256 * i;
            int r = idx >> 4, c4 = idx & 15;
            float4 v = xg[(rowBase + r) * 64 + kc * 16 + c4];
            __nv_bfloat16 h0, h1, h2, h3, l0, l1, l2, l3;
            split_bf(v.x, h0, l0); split_bf(v.y, h1, l1);
            split_bf(v.z, h2, l2); split_bf(v.w, h3, l3);
            *(uint2*)(Ah + r * 72 + c4 * 4) = make_uint2(pack_bf(h0, h1), pack_bf(h2, h3));
            *(uint2*)(Al + r * 72 + c4 * 4) = make_uint2(pack_bf(l0, l1), pack_bf(l2, l3));
        }
        __syncthreads();
        #pragma unroll
        for (int ks = 0; ks < 4; ks++) {
            int aoff = (m0 + g) * 72 + ks * 16 + 2 * t4;
            uint32_t ah[4], al[4];
            ah[0] = *(const uint32_t*)(Ah + aoff);
            ah[1] = *(const uint32_t*)(Ah + aoff + 8 * 72);
            ah[2] = *(const uint32_t*)(Ah + aoff + 8);
            ah[3] = *(const uint32_t*)(Ah + aoff + 8 * 72 + 8);
            al[0] = *(const uint32_t*)(Al + aoff);
            al[1] = *(const uint32_t*)(Al + aoff + 8 * 72);
            al[2] = *(const uint32_t*)(Al + aoff + 8);
            al[3] = *(const uint32_t*)(Al + aoff + 8 * 72 + 8);
            int fb = ((kc * 4 + ks) * 8) * 32 + lane;
            #pragma unroll
            for (int nt = 0; nt < 8; nt++) {
                uint2 bhv = g_FWBh[fb + nt * 32];
                uint2 blv = g_FWBl[fb + nt * 32];
                uint32_t bh[2] = {bhv.x, bhv.y};
                uint32_t bl[2] = {blv.x, blv.y};
                mma16816(acc[nt], ah, bh);
                mma16816(acc[nt], ah, bl);
                mma16816(acc[nt], al, bh);
            }
        }
    }
    // transpose C through smem, emit bf16 hi/lo planes [bci][64 rows][256 h]
    __syncthreads();
    float2* Cs = (float2*)smem;           // [c(32)][r pad 132]
    #pragma unroll
    for (int nt = 0; nt < 8; nt++) {
        int c = nt * 4 + t4;
        Cs[c * 132 + m0 + g]     = make_float2(acc[nt][0], acc[nt][1]);
        Cs[c * 132 + m0 + g + 8] = make_float2(acc[nt][2], acc[nt][3]);
    }
    __syncthreads();
    int bci = blockIdx.x >> 1, hh = blockIdx.x & 1;
    #pragma unroll
    for (int i = 0; i < 8; i++) {
        int idx = tid + 256 * i;              // 2048 = 32c x 64 r-pairs
        int c = idx >> 6, r2 = (idx & 63) * 2;
        float2 v0 = Cs[c * 132 + r2];
        float2 v1 = Cs[c * 132 + r2 + 1];
        __nv_bfloat16 h0, l0, h1, l1;
        size_t base = ((size_t)bci * 64 + 2 * c) * 256 + hh * 128 + r2;
        split_bf(v0.x, h0, l0); split_bf(v1.x, h1, l1);
        *(uint32_t*)(g_XwBh + base) = pack_bf(h0, h1);
        *(uint32_t*)(g_XwBl + base) = pack_bf(l0, l1);
        split_bf(v0.y, h0, l0); split_bf(v1.y, h1, l1);
        *(uint32_t*)(g_XwBh + base + 256) = pack_bf(h0, h1);
        *(uint32_t*)(g_XwBl + base + 256) = pack_bf(l0, l1);
    }
}

// ============== K2: fwd DFT along H; A frags global, B = pure memcpy ==============
#define FH_SMEM 33792
__global__ void __launch_bounds__(256) k_fwdH_m() {
    extern __shared__ unsigned char smem[];
    __nv_bfloat16* Bh = (__nv_bfloat16*)(smem);             // [32][264 pad]
    __nv_bfloat16* Bl = (__nv_bfloat16*)(smem + 16896);
    int tid = threadIdx.x, lane = tid & 31, wid = tid >> 5;
    int g = lane >> 2, t4 = lane & 3;
    int bci = blockIdx.x >> 1, nh = blockIdx.x & 1;
    int mt = wid & 3;
    int m0 = mt * 16, n0 = (wid >> 2) * 16;

    // stage B: 32 rows x 256, coalesced memcpy with pad
    {
        const uint4* sh = (const uint4*)(g_XwBh + ((size_t)bci * 64 + nh * 32) * 256);
        const uint4* sl = (const uint4*)(g_XwBl + ((size_t)bci * 64 + nh * 32) * 256);
        #pragma unroll
        for (int i = 0; i < 4; i++) {
            int idx = tid + 256 * i;              // 1024: row = idx>>5, c16 = idx&31
            int row = idx >> 5, c16 = idx & 31;
            *(uint4*)(Bh + row * 264 + c16 * 8) = sh[idx];
            *(uint4*)(Bl + row * 264 + c16 * 8) = sl[idx];
        }
    }
    __syncthreads();

    float accP[2][4], accQ[2][4];
    #pragma unroll
    for (int nt = 0; nt < 2; nt++)
        #pragma unroll
        for (int i = 0; i < 4; i++) { accP[nt][i] = 0.f; accQ[nt][i] = 0.f; }

    #pragma unroll
    for (int kc = 0; kc < 4; kc++) {
        #pragma unroll
        for (int ks = 0; ks < 4; ks++) {
            int fi = ((kc * 4 + ks) * 4 + mt) * 32 + lane;
            uint4 vrh = g_FHArh[fi], vrl = g_FHArl[fi];
            uint4 vih = g_FHAih[fi], vil = g_FHAil[fi];
            uint32_t arh[4] = {vrh.x, vrh.y, vrh.z, vrh.w};
            uint32_t arl[4] = {vrl.x, vrl.y, vrl.z, vrl.w};
            uint32_t aih[4] = {vih.x, vih.y, vih.z, vih.w};
            uint32_t ail[4] = {vil.x, vil.y, vil.z, vil.w};
            #pragma unroll
            for (int nt = 0; nt < 2; nt++) {
                int boff = (n0 + nt * 8 + g) * 264 + kc * 64 + ks * 16 + 2 * t4;
                uint32_t bh[2], bl[2];
                bh[0] = *(const uint32_t*)(Bh + boff);
                bh[1] = *(const uint32_t*)(Bh + boff + 8);
                bl[0] = *(const uint32_t*)(Bl + boff);
                bl[1] = *(const uint32_t*)(Bl + boff + 8);
                mma16816(accP[nt], arh, bh);
                mma16816(accP[nt], arh, bl);
                mma16816(accP[nt], arl, bh);
                mma16816(accQ[nt], aih, bh);
                mma16816(accQ[nt], aih, bl);
                mma16816(accQ[nt], ail, bh);
            }
        }
    }
    const float nrm = 1.0f / 256.0f;
    float2* gx = g_Xf + (size_t)bci * 64 * 32;
    #pragma unroll
    for (int nt = 0; nt < 2; nt++) {
        int col2 = nh * 16 + (n0 >> 1) + nt * 4 + t4;
        gx[(m0 + g) * 32 + col2] = make_float2((accP[nt][0] - accQ[nt][1]) * nrm,
                                               (accP[nt][1] + accQ[nt][0]) * nrm);
        gx[(m0 + g + 8) * 32 + col2] = make_float2((accP[nt][2] - accQ[nt][3]) * nrm,
                                                   (accP[nt][3] + accQ[nt][2]) * nrm);
    }
}

// ---- K3: channel mixing; emits bf16 hi/lo planes [bco][64 rows(2ky)][64 sx] ----
__global__ void __launch_bounds__(256) k_mix(const float* __restrict__ fs) {
    __shared__ float2 Ws[1024];
    __shared__ float2 Wes[1024];
    __shared__ float2 Xs[16][32];
    __shared__ float  ssm[16];
    int bid = blockIdx.x;
    int r = bid >> 10, kxy = bid & 1023;
    int kx = kxy >> 5, ky = kxy & 31;
    int sxg = r * 32 + kx;
    const float2* Wp  = g_Wt  + ((size_t)r << 20) + ((size_t)kxy << 10);
    const float2* Wep = g_Wet + ((size_t)r << 20) + ((size_t)kxy << 10);
    int t = threadIdx.x;
    #pragma unroll
    for (int i = 0; i < 4; i++) {
        Ws [t + 256*i] = Wp [t + 256*i];
        Wes[t + 256*i] = Wep[t + 256*i];
    }
    #pragma unroll
    for (int i = 0; i < 2; i++) {
        int p = t + 256*i;
        Xs[p >> 5][p & 31] = g_Xf[((size_t)p * 64 + sxg) * 32 + ky];
    }
    if (t < 16) {
        int idx;
        if (kx < 8 && ky < 8)        idx = 0;
        else if (kx < 16 && ky < 16) idx = (kx < 8) ? 1 : ((ky < 8) ? 2 : 3);
        else                         idx = (kx < 16) ? 4 : ((ky < 16) ? 5 : 6);
        ssm[t] = fs[t * 7 + idx];
    }
    __syncthreads();
    int co = t & 31, bh = t >> 5;
    float sb0 = ssm[bh], sb1 = ssm[bh + 8];
    float a0x = 0.f, a0y = 0.f, a1x = 0.f, a1y = 0.f;
    #pragma unroll 8
    for (int ci = 0; ci < 32; ci++) {
        float2 w  = Ws [ci * 32 + co];
        float2 we = Wes[ci * 32 + co];
        float2 x0 = Xs[bh][ci];
        float2 x1 = Xs[bh + 8][ci];
        float wr0 = fmaf(sb0, we.x, w.x), wi0 = fmaf(sb0, we.y, w.y);
        float wr1 = fmaf(sb1, we.x, w.x), wi1 = fmaf(sb1, we.y, w.y);
        a0x = fmaf(x0.x, wr0, fmaf(-x0.y, wi0, a0x));
        a0y = fmaf(x0.x, wi0, fmaf( x0.y, wr0, a0y));
        a1x = fmaf(x1.x, wr1, fmaf(-x1.y, wi1, a1x));
        a1y = fmaf(x1.x, wi1, fmaf( x1.y, wr1, a1y));
    }
    __nv_bfloat16 h, l;
    size_t b0 = (((size_t)bh * 32 + co) * 64 + 2 * ky) * 64 + sxg;
    split_bf(a0x, h, l); g_OfBh[b0] = h;      g_OfBl[b0] = l;
    split_bf(a0y, h, l); g_OfBh[b0 + 64] = h; g_OfBl[b0 + 64] = l;
    size_t b1 = (((size_t)(bh + 8) * 32 + co) * 64 + 2 * ky) * 64 + sxg;
    split_bf(a1x, h, l); g_OfBh[b1] = h;      g_OfBl[b1] = l;
    split_bf(a1y, h, l); g_OfBh[b1 + 64] = h; g_OfBl[b1 + 64] = l;
}

// ============== K4: inverse DFT along H; A frags global, B memcpy; emits bf16 planes ==============
#define IH_SMEM 18432
__global__ void __launch_bounds__(256) k_invH_m() {
    extern __shared__ unsigned char smem[];
    __nv_bfloat16* Bh = (__nv_bfloat16*)(smem);             // [64][72 pad]
    __nv_bfloat16* Bl = (__nv_bfloat16*)(smem + 9216);
    int tid = threadIdx.x, lane = tid & 31, wid = tid >> 5;
    int g = lane >> 2, t4 = lane & 3;
    int bco = blockIdx.x >> 2, hq = blockIdx.x & 3;
    int mt = wid & 3;
    int m0 = mt * 16, n0 = (wid >> 2) * 32;

    // stage B: 64 rows x 64, coalesced memcpy with pad
    {
        const uint4* sh = (const uint4*)(g_OfBh + (size_t)bco * 64 * 64);
        const uint4* sl = (const uint4*)(g_OfBl + (size_t)bco * 64 * 64);
        #pragma unroll
        for (int i = 0; i < 2; i++) {
            int idx = tid + 256 * i;              // 512: row = idx>>3, c = idx&7
            int row = idx >> 3, c = idx & 7;
            *(uint4*)(Bh + row * 72 + c * 8) = sh[idx];
            *(uint4*)(Bl + row * 72 + c * 8) = sl[idx];
        }
    }
    __syncthreads();

    float accP[4][4], accQ[4][4];
    #pragma unroll
    for (int nt = 0; nt < 4; nt++)
        #pragma unroll
        for (int i = 0; i < 4; i++) { accP[nt][i] = 0.f; accQ[nt][i] = 0.f; }

    #pragma unroll
    for (int ks = 0; ks < 4; ks++) {
        int fi = ((hq * 4 + ks) * 4 + mt) * 32 + lane;
        uint4 vrh = g_IHArh[fi], vrl = g_IHArl[fi];
        uint4 vih = g_IHAih[fi], vil = g_IHAil[fi];
        uint32_t arh[4] = {vrh.x, vrh.y, vrh.z, vrh.w};
        uint32_t arl[4] = {vrl.x, vrl.y, vrl.z, vrl.w};
        uint32_t aih[4] = {vih.x, vih.y, vih.z, vih.w};
        uint32_t ail[4] = {vil.x, vil.y, vil.z, vil.w};
        #pragma unroll
        for (int nt = 0; nt < 4; nt++) {
            int boff = (n0 + nt * 8 + g) * 72 + ks * 16 + 2 * t4;
            uint32_t bh[2], bl[2];
            bh[0] = *(const uint32_t*)(Bh + boff);
            bh[1] = *(const uint32_t*)(Bh + boff + 8);
            bl[0] = *(const uint32_t*)(Bl + boff);
            bl[1] = *(const uint32_t*)(Bl + boff + 8);
            mma16816(accP[nt], arh, bh);
            mma16816(accP[nt], arh, bl);
            mma16816(accP[nt], arl, bh);
            mma16816(accQ[nt], aih, bh);
            mma16816(accQ[nt], aih, bl);
            mma16816(accQ[nt], ail, bh);
        }
    }
    // emit bf16 hi/lo planes [row][64]: cols (2*col2, 2*col2+1) = (re, im)
    __nv_bfloat16* th = g_TmpAh + ((size_t)bco * 256 + hq * 64) * 64;
    __nv_bfloat16* tl = g_TmpAl + ((size_t)bco * 256 + hq * 64) * 64;
    #pragma unroll
    for (int nt = 0; nt < 4; nt++) {
        int col2 = (n0 >> 1) + nt * 4 + t4;
        float re0 = accP[nt][0] - accQ[nt][1], im0 = accP[nt][1] + accQ[nt][0];
        float re1 = accP[nt][2] - accQ[nt][3], im1 = accP[nt][3] + accQ[nt][2];
        __nv_bfloat16 h0, l0, h1, l1;
        split_bf(re0, h0, l0); split_bf(im0, h1, l1);
        *(uint32_t*)(th + (m0 + g) * 64 + 2 * col2) = pack_bf(h0, h1);
        *(uint32_t*)(tl + (m0 + g) * 64 + 2 * col2) = pack_bf(l0, l1);
        split_bf(re1, h0, l0); split_bf(im1, h1, l1);
        *(uint32_t*)(th + (m0 + g + 8) * 64 + 2 * col2) = pack_bf(h0, h1);
        *(uint32_t*)(tl + (m0 + g + 8) * 64 + 2 * col2) = pack_bf(l0, l1);
    }
}

// ============== K5: inverse real DFT along W; A memcpy, B frags global ==============
#define IR_SMEM 36864
__global__ void __launch_bounds__(256) k_irfftW_m(float* __restrict__ out) {
    extern __shared__ unsigned char smem[];
    __nv_bfloat16* Ah = (__nv_bfloat16*)(smem);             // [128][72 pad]
    __nv_bfloat16* Al = (__nv_bfloat16*)(smem + 18432);
    int tid = threadIdx.x, lane = tid & 31, wid = tid >> 5;
    int g = lane >> 2, t4 = lane & 3;
    int rg = blockIdx.x >> 1, nh = blockIdx.x & 1;
    size_t rowBase = (size_t)rg * 128;

    // stage A: 128 rows x 64, coalesced memcpy with pad
    {
        const uint4* sh = (const uint4*)(g_TmpAh + rowBase * 64);
        const uint4* sl = (const uint4*)(g_TmpAl + rowBase * 64);
        #pragma unroll
        for (int i = 0; i < 4; i++) {
            int idx = tid + 256 * i;              // 1024: row = idx>>3, c = idx&7
            int row = idx >> 3, c = idx & 7;
            *(uint4*)(Ah + row * 72 + c * 8) = sh[idx];
            *(uint4*)(Al + row * 72 + c * 8) = sl[idx];
        }
    }
    __syncthreads();

    int m0 = (wid >> 1) * 32;
    int n0 = (wid & 1) * 64;
    float acc[2][8][4];
    #pragma unroll
    for (int mt = 0; mt < 2; mt++)
        #pragma unroll
        for (int nt = 0; nt < 8; nt++)
            #pragma unroll
            for (int i = 0; i < 4; i++) acc[mt][nt][i] = 0.f;

    #pragma unroll
    for (int ks = 0; ks < 4; ks++) {
        uint32_t ah[2][4], al[2][4];
        #pragma unroll
        for (int mt = 0; mt < 2; mt++) {
            int aoff = (m0 + mt * 16 + g) * 72 + ks * 16 + 2 * t4;
            ah[mt][0] = *(const uint32_t*)(Ah + aoff);
            ah[mt][1] = *(const uint32_t*)(Ah + aoff + 8 * 72);
            ah[mt][2] = *(const uint32_t*)(Ah + aoff + 8);
            ah[mt][3] = *(const uint32_t*)(Ah + aoff + 8 * 72 + 8);
            al[mt][0] = *(const uint32_t*)(Al + aoff);
            al[mt][1] = *(const uint32_t*)(Al + aoff + 8 * 72);
            al[mt][2] = *(const uint32_t*)(Al + aoff + 8);
            al[mt][3] = *(const uint32_t*)(Al + aoff + 8 * 72 + 8);
        }
        #pragma unroll
        for (int nt = 0; nt < 8; nt++) {
            int fi = ((nh * 16 + (n0 >> 3) + nt) * 4 + ks) * 32 + lane;
            uint2 bhv = g_IRBh[fi];
            uint2 blv = g_IRBl[fi];
            uint32_t bh[2] = {bhv.x, bhv.y};
            uint32_t bl[2] = {blv.x, blv.y};
            #pragma unroll
            for (int mt = 0; mt < 2; mt++) {
                mma16816(acc[mt][nt], ah[mt], bh);
                mma16816(acc[mt][nt], ah[mt], bl);
                mma16816(acc[mt][nt], al[mt], bh);
            }
        }
    }
    #pragma unroll
    for (int mt = 0; mt < 2; mt++) {
        size_t r0 = rowBase + m0 + mt * 16 + g;
        #pragma unroll
        for (int nt = 0; nt < 8; nt++) {
            int col = nh * 128 + n0 + nt * 8 + 2 * t4;
            *(float2*)(out + r0 * 256 + col)       = make_float2(acc[mt][nt][0], acc[mt][nt][1]);
            *(float2*)(out + (r0 + 8) * 256 + col) = make_float2(acc[mt][nt][2], acc[mt][nt][3]);
        }
    }
}

extern "C" void kernel_launch(void* const* d_in, const int* in_sizes, int n_in,
                              void* d_out, int out_size) {
    const float* x   = (const float*)d_in[0];
    const float* fs  = (const float*)d_in[1];
    const float* w0  = (const float*)d_in[2];
    const float* w1  = (const float*)d_in[3];
    const float* we0 = (const float*)d_in[4];
    const float* we1 = (const float*)d_in[5];
    float* out = (float*)d_out;

    cudaFuncSetAttribute(k_fwdW_m,   cudaFuncAttributeMaxDynamicSharedMemorySize, FW_SMEM);
    cudaFuncSetAttribute(k_fwdH_m,   cudaFuncAttributeMaxDynamicSharedMemorySize, FH_SMEM);
    cudaFuncSetAttribute(k_invH_m,   cudaFuncAttributeMaxDynamicSharedMemorySize, IH_SMEM);
    cudaFuncSetAttribute(k_irfftW_m, cudaFuncAttributeMaxDynamicSharedMemorySize, IR_SMEM);

    k_init<<<48, 256>>>();
    k_wtrans<<<4096, 256>>>(w0, w1, we0, we1);
    k_fwdW_m<<<RTOT / 128, 256, FW_SMEM>>>(x);        // 1024 CTAs
    k_fwdH_m<<<Bsz * CIn * 2, 256, FH_SMEM>>>();      // 1024 CTAs
    k_mix<<<2 * 1024, 256>>>(fs);
    k_invH_m<<<Bsz * COn * 4, 256, IH_SMEM>>>();      // 2048 CTAs
    k_irfftW_m<<<RTOT / 64, 256, IR_SMEM>>>(out);     // 2048 CTAs
}

// round 10
// speedup vs baseline: 1.0881x; 1.0881x over previous
#include <cuda_runtime.h>
#include <cuda_bf16.h>
#include <math.h>
#include <stdint.h>

// Problem constants
#define Bsz 16
#define CIn 32
#define COn 32
#define Hn  256
#define Wn  256
#define KM  32
#define SXn 64
#define RTOT (Bsz*CIn*Hn)   // 131072 rows

// ============================ fragment-ordered constant tables ============================
__device__ __align__(16) uint2 g_FWBh[4*4*8*32], g_FWBl[4*4*8*32];
__device__ __align__(16) uint4 g_FHArh[4*4*4*32], g_FHArl[4*4*4*32],
                               g_FHAih[4*4*4*32], g_FHAil[4*4*4*32];
__device__ __align__(16) uint4 g_IHArh[4*4*4*32], g_IHArl[4*4*4*32],
                               g_IHAih[4*4*4*32], g_IHAil[4*4*4*32];
__device__ __align__(16) uint2 g_IRBh[2*16*4*32], g_IRBl[2*16*4*32];

// ============================ data buffers ============================
__device__ __align__(16) __nv_bfloat16 g_XwBh[(size_t)Bsz*CIn*64*256];  // fwdW out -> fwdH B
__device__ __align__(16) __nv_bfloat16 g_XwBl[(size_t)Bsz*CIn*64*256];
__device__ float2 g_Xf[(size_t)Bsz*CIn*SXn*KM];    // fwdH out [bci][sx][ky]
__device__ float2 g_OfT[(size_t)Bsz*COn*KM*SXn];   // mix out [bco][ky(32)][sx(64)]
__device__ float2 g_Tmp[(size_t)Bsz*COn*Hn*KM];    // invH out [bco*256+h][ky]
__device__ float2 g_Wt [2*1024*1024];
__device__ float2 g_Wet[2*1024*1024];

// ============================ helpers ============================
__device__ __forceinline__ uint32_t pack_bf(__nv_bfloat16 a, __nv_bfloat16 b) {
    return (uint32_t)__bfloat16_as_ushort(a) | ((uint32_t)__bfloat16_as_ushort(b) << 16);
}
__device__ __forceinline__ void split_bf(float v, __nv_bfloat16& h, __nv_bfloat16& l) {
    h = __float2bfloat16(v);
    l = __float2bfloat16(v - __bfloat162float(h));
}
__device__ __forceinline__ void mma16816(float* c, const uint32_t* a, const uint32_t* b) {
    asm volatile("mma.sync.aligned.m16n8k16.row.col.f32.bf16.bf16.f32 "
        "{%0,%1,%2,%3}, {%4,%5,%6,%7}, {%8,%9}, {%0,%1,%2,%3};"
        : "+f"(c[0]), "+f"(c[1]), "+f"(c[2]), "+f"(c[3])
        : "r"(a[0]), "r"(a[1]), "r"(a[2]), "r"(a[3]), "r"(b[0]), "r"(b[1]));
}

__global__ void k_init() {
    int t = blockIdx.x * blockDim.x + threadIdx.x;
    if (t < 4096) {                       // fwdW B frags
        int lane = t & 31, nt = (t >> 5) & 7, ks = (t >> 8) & 3, kc = t >> 10;
        int g = lane >> 2, t4 = lane & 3;
        int n = nt * 8 + g, q = n >> 1;
        uint32_t hv[2], lv[2];
        #pragma unroll
        for (int reg = 0; reg < 2; reg++) {
            int k0 = kc * 64 + ks * 16 + 2 * t4 + reg * 8;
            __nv_bfloat16 h0, l0, h1, l1;
            float s, c;
            sincospif((float)(q * k0) / 128.0f, &s, &c);
            split_bf((n & 1) ? -s : c, h0, l0);
            sincospif((float)(q * (k0 + 1)) / 128.0f, &s, &c);
            split_bf((n & 1) ? -s : c, h1, l1);
            hv[reg] = pack_bf(h0, h1); lv[reg] = pack_bf(l0, l1);
        }
        g_FWBh[t] = make_uint2(hv[0], hv[1]);
        g_FWBl[t] = make_uint2(lv[0], lv[1]);
    } else if (t < 6144) {                // fwdH A frags
        int e = t - 4096;
        int lane = e & 31, mt = (e >> 5) & 3, ks = (e >> 7) & 3, kc = e >> 9;
        int g = lane >> 2, t4 = lane & 3;
        uint32_t rh[4], rl[4], ih[4], il[4];
        #pragma unroll
        for (int reg = 0; reg < 4; reg++) {
            int sx = mt * 16 + g + (reg & 1) * 8;
            int kx = (sx < 32) ? sx : (192 + sx);
            int h0 = kc * 64 + ks * 16 + 2 * t4 + (reg >> 1) * 8;
            __nv_bfloat16 a, b, c1, d1, a2, b2, c2, d2;
            float s, c;
            sincospif((float)(kx * h0) / 128.0f, &s, &c);
            split_bf(c, a, b); split_bf(-s, c1, d1);
            sincospif((float)(kx * (h0 + 1)) / 128.0f, &s, &c);
            split_bf(c, a2, b2); split_bf(-s, c2, d2);
            rh[reg] = pack_bf(a, a2);  rl[reg] = pack_bf(b, b2);
            ih[reg] = pack_bf(c1, c2); il[reg] = pack_bf(d1, d2);
        }
        g_FHArh[e] = make_uint4(rh[0], rh[1], rh[2], rh[3]);
        g_FHArl[e] = make_uint4(rl[0], rl[1], rl[2], rl[3]);
        g_FHAih[e] = make_uint4(ih[0], ih[1], ih[2], ih[3]);
        g_FHAil[e] = make_uint4(il[0], il[1], il[2], il[3]);
    } else if (t < 8192) {                // invH A frags
        int e = t - 6144;
        int lane = e & 31, mt = (e >> 5) & 3, ks = (e >> 7) & 3, hq = e >> 9;
        int g = lane >> 2, t4 = lane & 3;
        uint32_t rh[4], rl[4], ih[4], il[4];
        #pragma unroll
        for (int reg = 0; reg < 4; reg++) {
            int h = hq * 64 + mt * 16 + g + (reg & 1) * 8;
            int s0 = ks * 16 + 2 * t4 + (reg >> 1) * 8;
            __nv_bfloat16 a, b, c1, d1, a2, b2, c2, d2;
            float s, c;
            int kx0 = (s0 < 32) ? s0 : (192 + s0);
            sincospif((float)(kx0 * h) / 128.0f, &s, &c);
            split_bf(c, a, b); split_bf(s, c1, d1);
            int s1 = s0 + 1;
            int kx1 = (s1 < 32) ? s1 : (192 + s1);
            sincospif((float)(kx1 * h) / 128.0f, &s, &c);
            split_bf(c, a2, b2); split_bf(s, c2, d2);
            rh[reg] = pack_bf(a, a2);  rl[reg] = pack_bf(b, b2);
            ih[reg] = pack_bf(c1, c2); il[reg] = pack_bf(d1, d2);
        }
        g_IHArh[e] = make_uint4(rh[0], rh[1], rh[2], rh[3]);
        g_IHArl[e] = make_uint4(rl[0], rl[1], rl[2], rl[3]);
        g_IHAih[e] = make_uint4(ih[0], ih[1], ih[2], ih[3]);
        g_IHAil[e] = make_uint4(il[0], il[1], il[2], il[3]);
    } else if (t < 12288) {               // irfftW B frags
        int e = t - 8192;
        int lane = e & 31, ks = (e >> 5) & 3, nt = (e >> 7) & 15, nh = e >> 11;
        int g = lane >> 2, t4 = lane & 3;
        int w = nh * 128 + nt * 8 + g;
        uint32_t hv[2], lv[2];
        #pragma unroll
        for (int reg = 0; reg < 2; reg++) {
            int j0 = ks * 16 + 2 * t4 + reg * 8;
            __nv_bfloat16 h0, l0, h1, l1;
            float s, c;
            int q0 = j0 >> 1;
            float al0 = ((q0 == 0) ? 1.0f : 2.0f) * (1.0f / 256.0f);
            sincospif((float)(q0 * w) / 128.0f, &s, &c);
            split_bf((j0 & 1) ? -al0 * s : al0 * c, h0, l0);
            int j1 = j0 + 1, q1 = j1 >> 1;
            float al1 = ((q1 == 0) ? 1.0f : 2.0f) * (1.0f / 256.0f);
            sincospif((float)(q1 * w) / 128.0f, &s, &c);
            split_bf((j1 & 1) ? -al1 * s : al1 * c, h1, l1);
            hv[reg] = pack_bf(h0, h1); lv[reg] = pack_bf(l0, l1);
        }
        g_IRBh[e] = make_uint2(hv[0], hv[1]);
        g_IRBl[e] = make_uint2(lv[0], lv[1]);
    }
}

// ---- K0b: transpose weights [p][kxy] -> [kxy][p] ----
__global__ void __launch_bounds__(256) k_wtrans(const float* __restrict__ w0,
                                                const float* __restrict__ w1,
                                                const float* __restrict__ we0,
                                                const float* __restrict__ we1) {
    __shared__ float2 sm[32][33];
    int bid = blockIdx.x;
    int arr = bid >> 10;
    int tile = bid & 1023;
    int I = tile >> 5, J = tile & 31;
    const float2* src = (const float2*)((arr == 0) ? w0 : (arr == 1) ? w1 : (arr == 2) ? we0 : we1);
    float2* dst = (arr < 2) ? (g_Wt + (size_t)arr * 1024 * 1024)
                            : (g_Wet + (size_t)(arr - 2) * 1024 * 1024);
    int t = threadIdx.x;
    int c = t & 31, rq = t >> 5;
    #pragma unroll
    for (int i = 0; i < 4; i++)
        sm[rq + 8 * i][c] = src[(size_t)(I * 32 + rq + 8 * i) * 1024 + J * 32 + c];
    __syncthreads();
    #pragma unroll
    for (int i = 0; i < 4; i++)
        dst[(size_t)(J * 32 + rq + 8 * i) * 1024 + I * 32 + c] = sm[c][rq + 8 * i];
}

// ============== K1: fwd DFT along W; B frags from global; emits bf16 planes ==============
#define FW_SMEM 36864
__global__ void __launch_bounds__(256) k_fwdW_m(const float* __restrict__ x) {
    extern __shared__ unsigned char smem[];
    __nv_bfloat16* Ah = (__nv_bfloat16*)(smem);
    __nv_bfloat16* Al = (__nv_bfloat16*)(smem + 18432);
    int tid = threadIdx.x, lane = tid & 31, wid = tid >> 5;
    int g = lane >> 2, t4 = lane & 3;
    size_t rowBase = (size_t)blockIdx.x * 128;
    int m0 = wid * 16;
    float acc[8][4];
    #pragma unroll
    for (int nt = 0; nt < 8; nt++)
        #pragma unroll
        for (int i = 0; i < 4; i++) acc[nt][i] = 0.f;

    const float4* xg = (const float4*)x;
    for (int kc = 0; kc < 4; kc++) {
        __syncthreads();
        #pragma unroll
        for (int i = 0; i < 8; i++) {
            int idx = tid + 256 * i;
            int r = idx >> 4, c4 = idx & 15;
            float4 v = xg[(rowBase + r) * 64 + kc * 16 + c4];
            __nv_bfloat16 h0, h1, h2, h3, l0, l1, l2, l3;
            split_bf(v.x, h0, l0); split_bf(v.y, h1, l1);
            split_bf(v.z, h2, l2); split_bf(v.w, h3, l3);
            *(uint2*)(Ah + r * 72 + c4 * 4) = make_uint2(pack_bf(h0, h1), pack_bf(h2, h3));
            *(uint2*)(Al + r * 72 + c4 * 4) = make_uint2(pack_bf(l0, l1), pack_bf(l2, l3));
        }
        __syncthreads();
        #pragma unroll
        for (int ks = 0; ks < 4; ks++) {
            int aoff = (m0 + g) * 72 + ks * 16 + 2 * t4;
            uint32_t ah[4], al[4];
            ah[0] = *(const uint32_t*)(Ah + aoff);
            ah[1] = *(const uint32_t*)(Ah + aoff + 8 * 72);
            ah[2] = *(const uint32_t*)(Ah + aoff + 8);
            ah[3] = *(const uint32_t*)(Ah + aoff + 8 * 72 + 8);
            al[0] = *(const uint32_t*)(Al + aoff);
            al[1] = *(const uint32_t*)(Al + aoff + 8 * 72);
            al[2] = *(const uint32_t*)(Al + aoff + 8);
            al[3] = *(const uint32_t*)(Al + aoff + 8 * 72 + 8);
            int fb = ((kc * 4 + ks) * 8) * 32 + lane;
            #pragma unroll
            for (int nt = 0; nt < 8; nt++) {
                uint2 bhv = g_FWBh[fb + nt * 32];
                uint2 blv = g_FWBl[fb + nt * 32];
                uint32_t bh[2] = {bhv.x, bhv.y};
                uint32_t bl[2] = {blv.x, blv.y};
                mma16816(acc[nt], ah, bh);
                mma16816(acc[nt], ah, bl);
                mma16816(acc[nt], al, bh);
            }
        }
    }
    // transpose C through smem, emit bf16 hi/lo planes [bci][64 rows][256 h]
    __syncthreads();
    float2* Cs = (float2*)smem;           // [c(32)][r pad 132]
    #pragma unroll
    for (int nt = 0; nt < 8; nt++) {
        int c = nt * 4 + t4;
        Cs[c * 132 + m0 + g]     = make_float2(acc[nt][0], acc[nt][1]);
        Cs[c * 132 + m0 + g + 8] = make_float2(acc[nt][2], acc[nt][3]);
    }
    __syncthreads();
    int bci = blockIdx.x >> 1, hh = blockIdx.x & 1;
    #pragma unroll
    for (int i = 0; i < 8; i++) {
        int idx = tid + 256 * i;              // 2048 = 32c x 64 r-pairs
        int c = idx >> 6, r2 = (idx & 63) * 2;
        float2 v0 = Cs[c * 132 + r2];
        float2 v1 = Cs[c * 132 + r2 + 1];
        __nv_bfloat16 h0, l0, h1, l1;
        size_t base = ((size_t)bci * 64 + 2 * c) * 256 + hh * 128 + r2;
        split_bf(v0.x, h0, l0); split_bf(v1.x, h1, l1);
        *(uint32_t*)(g_XwBh + base) = pack_bf(h0, h1);
        *(uint32_t*)(g_XwBl + base) = pack_bf(l0, l1);
        split_bf(v0.y, h0, l0); split_bf(v1.y, h1, l1);
        *(uint32_t*)(g_XwBh + base + 256) = pack_bf(h0, h1);
        *(uint32_t*)(g_XwBl + base + 256) = pack_bf(l0, l1);
    }
}

// ============== K2: fwd DFT along H; A frags global, B = pure memcpy ==============
#define FH_SMEM 33792
__global__ void __launch_bounds__(256) k_fwdH_m() {
    extern __shared__ unsigned char smem[];
    __nv_bfloat16* Bh = (__nv_bfloat16*)(smem);             // [32][264 pad]
    __nv_bfloat16* Bl = (__nv_bfloat16*)(smem + 16896);
    int tid = threadIdx.x, lane = tid & 31, wid = tid >> 5;
    int g = lane >> 2, t4 = lane & 3;
    int bci = blockIdx.x >> 1, nh = blockIdx.x & 1;
    int mt = wid & 3;
    int m0 = mt * 16, n0 = (wid >> 2) * 16;

    {
        const uint4* sh = (const uint4*)(g_XwBh + ((size_t)bci * 64 + nh * 32) * 256);
        const uint4* sl = (const uint4*)(g_XwBl + ((size_t)bci * 64 + nh * 32) * 256);
        #pragma unroll
        for (int i = 0; i < 4; i++) {
            int idx = tid + 256 * i;
            int row = idx >> 5, c16 = idx & 31;
            *(uint4*)(Bh + row * 264 + c16 * 8) = sh[idx];
            *(uint4*)(Bl + row * 264 + c16 * 8) = sl[idx];
        }
    }
    __syncthreads();

    float accP[2][4], accQ[2][4];
    #pragma unroll
    for (int nt = 0; nt < 2; nt++)
        #pragma unroll
        for (int i = 0; i < 4; i++) { accP[nt][i] = 0.f; accQ[nt][i] = 0.f; }

    #pragma unroll
    for (int kc = 0; kc < 4; kc++) {
        #pragma unroll
        for (int ks = 0; ks < 4; ks++) {
            int fi = ((kc * 4 + ks) * 4 + mt) * 32 + lane;
            uint4 vrh = g_FHArh[fi], vrl = g_FHArl[fi];
            uint4 vih = g_FHAih[fi], vil = g_FHAil[fi];
            uint32_t arh[4] = {vrh.x, vrh.y, vrh.z, vrh.w};
            uint32_t arl[4] = {vrl.x, vrl.y, vrl.z, vrl.w};
            uint32_t aih[4] = {vih.x, vih.y, vih.z, vih.w};
            uint32_t ail[4] = {vil.x, vil.y, vil.z, vil.w};
            #pragma unroll
            for (int nt = 0; nt < 2; nt++) {
                int boff = (n0 + nt * 8 + g) * 264 + kc * 64 + ks * 16 + 2 * t4;
                uint32_t bh[2], bl[2];
                bh[0] = *(const uint32_t*)(Bh + boff);
                bh[1] = *(const uint32_t*)(Bh + boff + 8);
                bl[0] = *(const uint32_t*)(Bl + boff);
                bl[1] = *(const uint32_t*)(Bl + boff + 8);
                mma16816(accP[nt], arh, bh);
                mma16816(accP[nt], arh, bl);
                mma16816(accP[nt], arl, bh);
                mma16816(accQ[nt], aih, bh);
                mma16816(accQ[nt], aih, bl);
                mma16816(accQ[nt], ail, bh);
            }
        }
    }
    const float nrm = 1.0f / 256.0f;
    float2* gx = g_Xf + (size_t)bci * 64 * 32;
    #pragma unroll
    for (int nt = 0; nt < 2; nt++) {
        int col2 = nh * 16 + (n0 >> 1) + nt * 4 + t4;
        gx[(m0 + g) * 32 + col2] = make_float2((accP[nt][0] - accQ[nt][1]) * nrm,
                                               (accP[nt][1] + accQ[nt][0]) * nrm);
        gx[(m0 + g + 8) * 32 + col2] = make_float2((accP[nt][2] - accQ[nt][3]) * nrm,
                                                   (accP[nt][3] + accQ[nt][2]) * nrm);
    }
}

// ---- K3: channel mixing; writes f32 g_OfT[bco][ky][sx] (R8 layout) ----
__global__ void __launch_bounds__(256) k_mix(const float* __restrict__ fs) {
    __shared__ float2 Ws[1024];
    __shared__ float2 Wes[1024];
    __shared__ float2 Xs[16][32];
    __shared__ float  ssm[16];
    int bid = blockIdx.x;
    int r = bid >> 10, kxy = bid & 1023;
    int kx = kxy >> 5, ky = kxy & 31;
    int sxg = r * 32 + kx;
    const float2* Wp  = g_Wt  + ((size_t)r << 20) + ((size_t)kxy << 10);
    const float2* Wep = g_Wet + ((size_t)r << 20) + ((size_t)kxy << 10);
    int t = threadIdx.x;
    #pragma unroll
    for (int i = 0; i < 4; i++) {
        Ws [t + 256*i] = Wp [t + 256*i];
        Wes[t + 256*i] = Wep[t + 256*i];
    }
    #pragma unroll
    for (int i = 0; i < 2; i++) {
        int p = t + 256*i;
        Xs[p >> 5][p & 31] = g_Xf[((size_t)p * 64 + sxg) * 32 + ky];
    }
    if (t < 16) {
        int idx;
        if (kx < 8 && ky < 8)        idx = 0;
        else if (kx < 16 && ky < 16) idx = (kx < 8) ? 1 : ((ky < 8) ? 2 : 3);
        else                         idx = (kx < 16) ? 4 : ((ky < 16) ? 5 : 6);
        ssm[t] = fs[t * 7 + idx];
    }
    __syncthreads();
    int co = t & 31, bh = t >> 5;
    float sb0 = ssm[bh], sb1 = ssm[bh + 8];
    float a0x = 0.f, a0y = 0.f, a1x = 0.f, a1y = 0.f;
    #pragma unroll 8
    for (int ci = 0; ci < 32; ci++) {
        float2 w  = Ws [ci * 32 + co];
        float2 we = Wes[ci * 32 + co];
        float2 x0 = Xs[bh][ci];
        float2 x1 = Xs[bh + 8][ci];
        float wr0 = fmaf(sb0, we.x, w.x), wi0 = fmaf(sb0, we.y, w.y);
        float wr1 = fmaf(sb1, we.x, w.x), wi1 = fmaf(sb1, we.y, w.y);
        a0x = fmaf(x0.x, wr0, fmaf(-x0.y, wi0, a0x));
        a0y = fmaf(x0.x, wi0, fmaf( x0.y, wr0, a0y));
        a1x = fmaf(x1.x, wr1, fmaf(-x1.y, wi1, a1x));
        a1y = fmaf(x1.x, wi1, fmaf( x1.y, wr1, a1y));
    }
    g_OfT[(((size_t)bh       * 32 + co) * 32 + ky) * 64 + sxg] = make_float2(a0x, a0y);
    g_OfT[(((size_t)(bh + 8) * 32 + co) * 32 + ky) * 64 + sxg] = make_float2(a1x, a1y);
}

// ============== K4: inverse DFT along H; A frags global, B split-staged from f32 ==============
#define IH_SMEM 18432
__global__ void __launch_bounds__(256) k_invH_m() {
    extern __shared__ unsigned char smem[];
    __nv_bfloat16* Bh = (__nv_bfloat16*)(smem);             // [64][72 pad]
    __nv_bfloat16* Bl = (__nv_bfloat16*)(smem + 9216);
    int tid = threadIdx.x, lane = tid & 31, wid = tid >> 5;
    int g = lane >> 2, t4 = lane & 3;
    int bco = blockIdx.x >> 2, hq = blockIdx.x & 3;
    int mt = wid & 3;
    int m0 = mt * 16, n0 = (wid >> 2) * 32;

    // stage B = O^T slice from f32 g_OfT: [64 real ky rows][72 pad sx]
    {
        const float2* Op = g_OfT + (size_t)bco * 32 * 64;
        #pragma unroll
        for (int i = 0; i < 8; i++) {
            int idx = tid + 256 * i;
            int ky = idx >> 6, sx = idx & 63;
            float2 v = Op[idx];
            __nv_bfloat16 rh, rl, ih, il;
            split_bf(v.x, rh, rl); split_bf(v.y, ih, il);
            Bh[(2*ky)   * 72 + sx] = rh;  Bl[(2*ky)   * 72 + sx] = rl;
            Bh[(2*ky+1) * 72 + sx] = ih;  Bl[(2*ky+1) * 72 + sx] = il;
        }
    }
    __syncthreads();

    float accP[4][4], accQ[4][4];
    #pragma unroll
    for (int nt = 0; nt < 4; nt++)
        #pragma unroll
        for (int i = 0; i < 4; i++) { accP[nt][i] = 0.f; accQ[nt][i] = 0.f; }

    #pragma unroll
    for (int ks = 0; ks < 4; ks++) {
        int fi = ((hq * 4 + ks) * 4 + mt) * 32 + lane;
        uint4 vrh = g_IHArh[fi], vrl = g_IHArl[fi];
        uint4 vih = g_IHAih[fi], vil = g_IHAil[fi];
        uint32_t arh[4] = {vrh.x, vrh.y, vrh.z, vrh.w};
        uint32_t arl[4] = {vrl.x, vrl.y, vrl.z, vrl.w};
        uint32_t aih[4] = {vih.x, vih.y, vih.z, vih.w};
        uint32_t ail[4] = {vil.x, vil.y, vil.z, vil.w};
        #pragma unroll
        for (int nt = 0; nt < 4; nt++) {
            int boff = (n0 + nt * 8 + g) * 72 + ks * 16 + 2 * t4;
            uint32_t bh[2], bl[2];
            bh[0] = *(const uint32_t*)(Bh + boff);
            bh[1] = *(const uint32_t*)(Bh + boff + 8);
            bl[0] = *(const uint32_t*)(Bl + boff);
            bl[1] = *(const uint32_t*)(Bl + boff + 8);
            mma16816(accP[nt], arh, bh);
            mma16816(accP[nt], arh, bl);
            mma16816(accP[nt], arl, bh);
            mma16816(accQ[nt], aih, bh);
            mma16816(accQ[nt], aih, bl);
            mma16816(accQ[nt], ail, bh);
        }
    }
    float2* gt = g_Tmp + (size_t)bco * 256 * 32 + (size_t)hq * 64 * 32;
    #pragma unroll
    for (int nt = 0; nt < 4; nt++) {
        int col2 = (n0 >> 1) + nt * 4 + t4;
        gt[(m0 + g) * 32 + col2] = make_float2(accP[nt][0] - accQ[nt][1],
                                               accP[nt][1] + accQ[nt][0]);
        gt[(m0 + g + 8) * 32 + col2] = make_float2(accP[nt][2] - accQ[nt][3],
                                                   accP[nt][3] + accQ[nt][2]);
    }
}

// ============== K5: inverse real DFT along W; A split-staged from f32, B frags global ==============
#define IR_SMEM 36864
__global__ void __launch_bounds__(256) k_irfftW_m(float* __restrict__ out) {
    extern __shared__ unsigned char smem[];
    __nv_bfloat16* Ah = (__nv_bfloat16*)(smem);             // [128][72 pad]
    __nv_bfloat16* Al = (__nv_bfloat16*)(smem + 18432);
    int tid = threadIdx.x, lane = tid & 31, wid = tid >> 5;
    int g = lane >> 2, t4 = lane & 3;
    int rg = blockIdx.x >> 1, nh = blockIdx.x & 1;
    size_t rowBase = (size_t)rg * 128;

    // stage A: 128 rows x 64, from f32 g_Tmp with split
    {
        const float4* ag = (const float4*)g_Tmp;
        #pragma unroll
        for (int i = 0; i < 8; i++) {
            int idx = tid + 256 * i;
            int r = idx >> 4, c4 = idx & 15;
            float4 v = ag[(rowBase + r) * 16 + c4];
            __nv_bfloat16 h0, h1, h2, h3, l0, l1, l2, l3;
            split_bf(v.x, h0, l0); split_bf(v.y, h1, l1);
            split_bf(v.z, h2, l2); split_bf(v.w, h3, l3);
            *(uint2*)(Ah + r * 72 + c4 * 4) = make_uint2(pack_bf(h0, h1), pack_bf(h2, h3));
            *(uint2*)(Al + r * 72 + c4 * 4) = make_uint2(pack_bf(l0, l1), pack_bf(l2, l3));
        }
    }
    __syncthreads();

    int m0 = (wid >> 1) * 32;
    int n0 = (wid & 1) * 64;
    float acc[2][8][4];
    #pragma unroll
    for (int mt = 0; mt < 2; mt++)
        #pragma unroll
        for (int nt = 0; nt < 8; nt++)
            #pragma unroll
            for (int i = 0; i < 4; i++) acc[mt][nt][i] = 0.f;

    #pragma unroll
    for (int ks = 0; ks < 4; ks++) {
        uint32_t ah[2][4], al[2][4];
        #pragma unroll
        for (int mt = 0; mt < 2; mt++) {
            int aoff = (m0 + mt * 16 + g) * 72 + ks * 16 + 2 * t4;
            ah[mt][0] = *(const uint32_t*)(Ah + aoff);
            ah[mt][1] = *(const uint32_t*)(Ah + aoff + 8 * 72);
            ah[mt][2] = *(const uint32_t*)(Ah + aoff + 8);
            ah[mt][3] = *(const uint32_t*)(Ah + aoff + 8 * 72 + 8);
            al[mt][0] = *(const uint32_t*)(Al + aoff);
            al[mt][1] = *(const uint32_t*)(Al + aoff + 8 * 72);
            al[mt][2] = *(const uint32_t*)(Al + aoff + 8);
            al[mt][3] = *(const uint32_t*)(Al + aoff + 8 * 72 + 8);
        }
        #pragma unroll
        for (int nt = 0; nt < 8; nt++) {
            int fi = ((nh * 16 + (n0 >> 3) + nt) * 4 + ks) * 32 + lane;
            uint2 bhv = g_IRBh[fi];
            uint2 blv = g_IRBl[fi];
            uint32_t bh[2] = {bhv.x, bhv.y};
            uint32_t bl[2] = {blv.x, blv.y};
            #pragma unroll
            for (int mt = 0; mt < 2; mt++) {
                mma16816(acc[mt][nt], ah[mt], bh);
                mma16816(acc[mt][nt], ah[mt], bl);
                mma16816(acc[mt][nt], al[mt], bh);
            }
        }
    }
    #pragma unroll
    for (int mt = 0; mt < 2; mt++) {
        size_t r0 = rowBase + m0 + mt * 16 + g;
        #pragma unroll
        for (int nt = 0; nt < 8; nt++) {
            int col = nh * 128 + n0 + nt * 8 + 2 * t4;
            *(float2*)(out + r0 * 256 + col)       = make_float2(acc[mt][nt][0], acc[mt][nt][1]);
            *(float2*)(out + (r0 + 8) * 256 + col) = make_float2(acc[mt][nt][2], acc[mt][nt][3]);
        }
    }
}

extern "C" void kernel_launch(void* const* d_in, const int* in_sizes, int n_in,
                              void* d_out, int out_size) {
    const float* x   = (const float*)d_in[0];
    const float* fs  = (const float*)d_in[1];
    const float* w0  = (const float*)d_in[2];
    const float* w1  = (const float*)d_in[3];
    const float* we0 = (const float*)d_in[4];
    const float* we1 = (const float*)d_in[5];
    float* out = (float*)d_out;

    cudaFuncSetAttribute(k_fwdW_m,   cudaFuncAttributeMaxDynamicSharedMemorySize, FW_SMEM);
    cudaFuncSetAttribute(k_fwdH_m,   cudaFuncAttributeMaxDynamicSharedMemorySize, FH_SMEM);
    cudaFuncSetAttribute(k_invH_m,   cudaFuncAttributeMaxDynamicSharedMemorySize, IH_SMEM);
    cudaFuncSetAttribute(k_irfftW_m, cudaFuncAttributeMaxDynamicSharedMemorySize, IR_SMEM);

    k_init<<<48, 256>>>();
    k_wtrans<<<4096, 256>>>(w0, w1, we0, we1);
    k_fwdW_m<<<RTOT / 128, 256, FW_SMEM>>>(x);        // 1024 CTAs
    k_fwdH_m<<<Bsz * CIn * 2, 256, FH_SMEM>>>();      // 1024 CTAs
    k_mix<<<2 * 1024, 256>>>(fs);
    k_invH_m<<<Bsz * COn * 4, 256, IH_SMEM>>>();      // 2048 CTAs
    k_irfftW_m<<<RTOT / 64, 256, IR_SMEM>>>(out);     // 2048 CTAs
}

// round 11
// speedup vs baseline: 1.2917x; 1.1872x over previous
#include <cuda_runtime.h>
#include <cuda_bf16.h>
#include <math.h>
#include <stdint.h>

// Problem constants
#define Bsz 16
#define CIn 32
#define COn 32
#define Hn  256
#define Wn  256
#define KM  32
#define SXn 64
#define RTOT (Bsz*CIn*Hn)   // 131072 rows

// ============================ tables ============================
__device__ float2 g_TV [64*32];   // [sx][v] e^{-2pi i kx(sx) v/256}
__device__ float2 g_E8 [8*8];
__device__ float2 g_E8i[8*8];
// fragment-ordered constant tables (validated in R9/R10)
__device__ __align__(16) uint2 g_FWBh[4*4*8*32], g_FWBl[4*4*8*32];   // fwdW B frags
__device__ __align__(16) uint2 g_IRBh[2*16*4*32], g_IRBl[2*16*4*32]; // irfftW B frags

// ============================ scratch ============================
__device__ float2 g_Xw[(size_t)RTOT*KM];          // fwdW out [row][k]
__device__ float2 g_Xf[(size_t)Bsz*CIn*SXn*KM];   // fwdH out [bci][sx][k]
__device__ float2 g_Of[(size_t)Bsz*COn*SXn*KM];   // mix out  [bco][sx][k]
__device__ float2 g_Tmp[(size_t)Bsz*COn*Hn*KM];   // invH out [row][k]
__device__ float2 g_Wt [2*1024*1024];
__device__ float2 g_Wet[2*1024*1024];

// ============================ helpers ============================
__device__ __forceinline__ uint32_t pack_bf(__nv_bfloat16 a, __nv_bfloat16 b) {
    return (uint32_t)__bfloat16_as_ushort(a) | ((uint32_t)__bfloat16_as_ushort(b) << 16);
}
__device__ __forceinline__ void split_bf(float v, __nv_bfloat16& h, __nv_bfloat16& l) {
    h = __float2bfloat16(v);
    l = __float2bfloat16(v - __bfloat162float(h));
}
__device__ __forceinline__ void mma16816(float* c, const uint32_t* a, const uint32_t* b) {
    asm volatile("mma.sync.aligned.m16n8k16.row.col.f32.bf16.bf16.f32 "
        "{%0,%1,%2,%3}, {%4,%5,%6,%7}, {%8,%9}, {%0,%1,%2,%3};"
        : "+f"(c[0]), "+f"(c[1]), "+f"(c[2]), "+f"(c[3])
        : "r"(a[0]), "r"(a[1]), "r"(a[2]), "r"(a[3]), "r"(b[0]), "r"(b[1]));
}

__global__ void k_init() {
    int t = blockIdx.x * blockDim.x + threadIdx.x;
    if (t < 2048) {                     // g_TV
        int sx = t >> 5, v = t & 31;
        int kx = (sx < 32) ? sx : (192 + sx);
        float s, c; sincospif((float)(kx * v) / 128.0f, &s, &c);
        g_TV[t] = make_float2(c, -s);
    }
    int t1 = t - 2048;
    if (t1 >= 0 && t1 < 64) {           // E8 / E8i
        int m = t1 >> 3, a = t1 & 7;
        float s, c; sincospif((float)(m * a) / 4.0f, &s, &c);
        g_E8 [t1] = make_float2(c, -s);
        g_E8i[t1] = make_float2(c,  s);
    }
    int t2 = t1 - 64;
    if (t2 >= 0 && t2 < 4096) {         // fwdW B frags
        int lane = t2 & 31, nt = (t2 >> 5) & 7, ks = (t2 >> 8) & 3, kc = t2 >> 10;
        int g = lane >> 2, t4 = lane & 3;
        int n = nt * 8 + g, q = n >> 1;
        uint32_t hv[2], lv[2];
        #pragma unroll
        for (int reg = 0; reg < 2; reg++) {
            int k0 = kc * 64 + ks * 16 + 2 * t4 + reg * 8;
            __nv_bfloat16 h0, l0, h1, l1;
            float s, c;
            sincospif((float)(q * k0) / 128.0f, &s, &c);
            split_bf((n & 1) ? -s : c, h0, l0);
            sincospif((float)(q * (k0 + 1)) / 128.0f, &s, &c);
            split_bf((n & 1) ? -s : c, h1, l1);
            hv[reg] = pack_bf(h0, h1); lv[reg] = pack_bf(l0, l1);
        }
        g_FWBh[t2] = make_uint2(hv[0], hv[1]);
        g_FWBl[t2] = make_uint2(lv[0], lv[1]);
    }
    int t3 = t2 - 4096;
    if (t3 >= 0 && t3 < 4096) {         // irfftW B frags
        int lane = t3 & 31, ks = (t3 >> 5) & 3, nt = (t3 >> 7) & 15, nh = t3 >> 11;
        int g = lane >> 2, t4 = lane & 3;
        int w = nh * 128 + nt * 8 + g;
        uint32_t hv[2], lv[2];
        #pragma unroll
        for (int reg = 0; reg < 2; reg++) {
            int j0 = ks * 16 + 2 * t4 + reg * 8;
            __nv_bfloat16 h0, l0, h1, l1;
            float s, c;
            int q0 = j0 >> 1;
            float al0 = ((q0 == 0) ? 1.0f : 2.0f) * (1.0f / 256.0f);
            sincospif((float)(q0 * w) / 128.0f, &s, &c);
            split_bf((j0 & 1) ? -al0 * s : al0 * c, h0, l0);
            int j1 = j0 + 1, q1 = j1 >> 1;
            float al1 = ((q1 == 0) ? 1.0f : 2.0f) * (1.0f / 256.0f);
            sincospif((float)(q1 * w) / 128.0f, &s, &c);
            split_bf((j1 & 1) ? -al1 * s : al1 * c, h1, l1);
            hv[reg] = pack_bf(h0, h1); lv[reg] = pack_bf(l0, l1);
        }
        g_IRBh[t3] = make_uint2(hv[0], hv[1]);
        g_IRBl[t3] = make_uint2(lv[0], lv[1]);
    }
}

// ---- K0b: transpose weights [p][kxy] -> [kxy][p] ----
__global__ void __launch_bounds__(256) k_wtrans(const float* __restrict__ w0,
                                                const float* __restrict__ w1,
                                                const float* __restrict__ we0,
                                                const float* __restrict__ we1) {
    __shared__ float2 sm[32][33];
    int bid = blockIdx.x;
    int arr = bid >> 10;
    int tile = bid & 1023;
    int I = tile >> 5, J = tile & 31;
    const float2* src = (const float2*)((arr == 0) ? w0 : (arr == 1) ? w1 : (arr == 2) ? we0 : we1);
    float2* dst = (arr < 2) ? (g_Wt + (size_t)arr * 1024 * 1024)
                            : (g_Wet + (size_t)(arr - 2) * 1024 * 1024);
    int t = threadIdx.x;
    int c = t & 31, rq = t >> 5;
    #pragma unroll
    for (int i = 0; i < 4; i++)
        sm[rq + 8 * i][c] = src[(size_t)(I * 32 + rq + 8 * i) * 1024 + J * 32 + c];
    __syncthreads();
    #pragma unroll
    for (int i = 0; i < 4; i++)
        dst[(size_t)(J * 32 + rq + 8 * i) * 1024 + I * 32 + c] = sm[c][rq + 8 * i];
}

// ============== K1: fwd DFT along W via mma.sync; B from global frags ==============
#define FW_SMEM 36864
__global__ void __launch_bounds__(256) k_fwdW_m(const float* __restrict__ x) {
    extern __shared__ unsigned char smem[];
    __nv_bfloat16* Ah = (__nv_bfloat16*)(smem);
    __nv_bfloat16* Al = (__nv_bfloat16*)(smem + 18432);
    int tid = threadIdx.x, lane = tid & 31, wid = tid >> 5;
    int g = lane >> 2, t4 = lane & 3;
    size_t rowBase = (size_t)blockIdx.x * 128;
    int m0 = wid * 16;
    float acc[8][4];
    #pragma unroll
    for (int nt = 0; nt < 8; nt++)
        #pragma unroll
        for (int i = 0; i < 4; i++) acc[nt][i] = 0.f;

    const float4* xg = (const float4*)x;
    for (int kc = 0; kc < 4; kc++) {
        __syncthreads();
        #pragma unroll
        for (int i = 0; i < 8; i++) {
            int idx = tid + 256 * i;
            int r = idx >> 4, c4 = idx & 15;
            float4 v = xg[(rowBase + r) * 64 + kc * 16 + c4];
            __nv_bfloat16 h0, h1, h2, h3, l0, l1, l2, l3;
            split_bf(v.x, h0, l0); split_bf(v.y, h1, l1);
            split_bf(v.z, h2, l2); split_bf(v.w, h3, l3);
            *(uint2*)(Ah + r * 72 + c4 * 4) = make_uint2(pack_bf(h0, h1), pack_bf(h2, h3));
            *(uint2*)(Al + r * 72 + c4 * 4) = make_uint2(pack_bf(l0, l1), pack_bf(l2, l3));
        }
        __syncthreads();
        #pragma unroll
        for (int ks = 0; ks < 4; ks++) {
            int aoff = (m0 + g) * 72 + ks * 16 + 2 * t4;
            uint32_t ah[4], al[4];
            ah[0] = *(const uint32_t*)(Ah + aoff);
            ah[1] = *(const uint32_t*)(Ah + aoff + 8 * 72);
            ah[2] = *(const uint32_t*)(Ah + aoff + 8);
            ah[3] = *(const uint32_t*)(Ah + aoff + 8 * 72 + 8);
            al[0] = *(const uint32_t*)(Al + aoff);
            al[1] = *(const uint32_t*)(Al + aoff + 8 * 72);
            al[2] = *(const uint32_t*)(Al + aoff + 8);
            al[3] = *(const uint32_t*)(Al + aoff + 8 * 72 + 8);
            int fb = ((kc * 4 + ks) * 8) * 32 + lane;
            #pragma unroll
            for (int nt = 0; nt < 8; nt++) {
                uint2 bhv = g_FWBh[fb + nt * 32];
                uint2 blv = g_FWBl[fb + nt * 32];
                uint32_t bh[2] = {bhv.x, bhv.y};
                uint32_t bl[2] = {blv.x, blv.y};
                mma16816(acc[nt], ah, bh);
                mma16816(acc[nt], ah, bl);
                mma16816(acc[nt], al, bh);
            }
        }
    }
    // epilogue: f32 interleaved g_Xw[row][32] (R6 layout)
    float2* gx = g_Xw;
    #pragma unroll
    for (int nt = 0; nt < 8; nt++) {
        int col = nt * 4 + t4;
        gx[(rowBase + m0 + g) * 32 + col]     = make_float2(acc[nt][0], acc[nt][1]);
        gx[(rowBase + m0 + g + 8) * 32 + col] = make_float2(acc[nt][2], acc[nt][3]);
    }
}

// ---- K2: fwd DFT along H (scalar radix-8, R6 verbatim) ----
__global__ void __launch_bounds__(256) k_fwdH() {
    __shared__ float2 Xs[256][8];
    __shared__ float2 Ys[32][8][8];
    __shared__ float2 E8s[8][8];
    int t = threadIdx.x;
    int bci = blockIdx.x >> 2, kq = blockIdx.x & 3;
    const float2* Xp = g_Xw + (size_t)bci * 256 * 32 + kq * 8;
    #pragma unroll
    for (int i = 0; i < 8; i++) {
        int idx = t + 256*i;
        Xs[idx >> 3][idx & 7] = Xp[(size_t)(idx >> 3) * 32 + (idx & 7)];
    }
    if (t < 64) ((float2*)E8s)[t] = g_E8[t];
    __syncthreads();
    int v = t >> 3, k = t & 7;
    {
        float2 xa[8];
        #pragma unroll
        for (int a = 0; a < 8; a++) xa[a] = Xs[v + 32*a][k];
        #pragma unroll
        for (int m = 0; m < 8; m++) {
            float yr = 0.f, yi = 0.f;
            #pragma unroll
            for (int a = 0; a < 8; a++) {
                float2 e = E8s[m][a];
                yr = fmaf(xa[a].x, e.x, fmaf(-xa[a].y, e.y, yr));
                yi = fmaf(xa[a].x, e.y, fmaf( xa[a].y, e.x, yi));
            }
            Ys[v][m][k] = make_float2(yr, yi);
        }
    }
    __syncthreads();
    int k2 = t & 7, sx2 = t >> 3;
    int m = sx2 & 7;
    float a0x = 0.f, a0y = 0.f, a1x = 0.f, a1y = 0.f;
    #pragma unroll 8
    for (int vv = 0; vv < 32; vv++) {
        float2 y  = Ys[vv][m][k2];
        float2 t0 = g_TV[sx2 * 32 + vv];
        float2 t1 = g_TV[(sx2 + 32) * 32 + vv];
        a0x = fmaf(y.x, t0.x, fmaf(-y.y, t0.y, a0x));
        a0y = fmaf(y.x, t0.y, fmaf( y.y, t0.x, a0y));
        a1x = fmaf(y.x, t1.x, fmaf(-y.y, t1.y, a1x));
        a1y = fmaf(y.x, t1.y, fmaf( y.y, t1.x, a1y));
    }
    const float nrm = 1.0f / 256.0f;
    g_Xf[((size_t)bci * 64 + sx2)      * 32 + kq * 8 + k2] = make_float2(a0x * nrm, a0y * nrm);
    g_Xf[((size_t)bci * 64 + sx2 + 32) * 32 + kq * 8 + k2] = make_float2(a1x * nrm, a1y * nrm);
}

// ---- K3: channel mixing (R6 verbatim) ----
__global__ void __launch_bounds__(256) k_mix(const float* __restrict__ fs) {
    __shared__ float2 Ws[1024];
    __shared__ float2 Wes[1024];
    __shared__ float2 Xs[16][32];
    __shared__ float  ssm[16];
    int bid = blockIdx.x;
    int r = bid >> 10, kxy = bid & 1023;
    int kx = kxy >> 5, ky = kxy & 31;
    int sxg = r * 32 + kx;
    const float2* Wp  = g_Wt  + ((size_t)r << 20) + ((size_t)kxy << 10);
    const float2* Wep = g_Wet + ((size_t)r << 20) + ((size_t)kxy << 10);
    int t = threadIdx.x;
    #pragma unroll
    for (int i = 0; i < 4; i++) {
        Ws [t + 256*i] = Wp [t + 256*i];
        Wes[t + 256*i] = Wep[t + 256*i];
    }
    #pragma unroll
    for (int i = 0; i < 2; i++) {
        int p = t + 256*i;
        Xs[p >> 5][p & 31] = g_Xf[((size_t)p * 64 + sxg) * 32 + ky];
    }
    if (t < 16) {
        int idx;
        if (kx < 8 && ky < 8)        idx = 0;
        else if (kx < 16 && ky < 16) idx = (kx < 8) ? 1 : ((ky < 8) ? 2 : 3);
        else                         idx = (kx < 16) ? 4 : ((ky < 16) ? 5 : 6);
        ssm[t] = fs[t * 7 + idx];
    }
    __syncthreads();
    int co = t & 31, bh = t >> 5;
    float sb0 = ssm[bh], sb1 = ssm[bh + 8];
    float a0x = 0.f, a0y = 0.f, a1x = 0.f, a1y = 0.f;
    #pragma unroll 8
    for (int ci = 0; ci < 32; ci++) {
        float2 w  = Ws [ci * 32 + co];
        float2 we = Wes[ci * 32 + co];
        float2 x0 = Xs[bh][ci];
        float2 x1 = Xs[bh + 8][ci];
        float wr0 = fmaf(sb0, we.x, w.x), wi0 = fmaf(sb0, we.y, w.y);
        float wr1 = fmaf(sb1, we.x, w.x), wi1 = fmaf(sb1, we.y, w.y);
        a0x = fmaf(x0.x, wr0, fmaf(-x0.y, wi0, a0x));
        a0y = fmaf(x0.x, wi0, fmaf( x0.y, wr0, a0y));
        a1x = fmaf(x1.x, wr1, fmaf(-x1.y, wi1, a1x));
        a1y = fmaf(x1.x, wi1, fmaf( x1.y, wr1, a1y));
    }
    g_Of[(((size_t)bh       * 32 + co) * 64 + sxg) * 32 + ky] = make_float2(a0x, a0y);
    g_Of[(((size_t)(bh + 8) * 32 + co) * 64 + sxg) * 32 + ky] = make_float2(a1x, a1y);
}

// ---- K4: inverse DFT along H (scalar radix-8, R6 verbatim) ----
__global__ void __launch_bounds__(256) k_invH() {
    __shared__ float2 Ofs[64][8];
    __shared__ float2 E8is[8][8];
    int t = threadIdx.x;
    int bco = blockIdx.x >> 2, kq = blockIdx.x & 3;
    const float2* Op = g_Of + (size_t)bco * 64 * 32 + kq * 8;
    #pragma unroll
    for (int i = 0; i < 2; i++) {
        int idx = t + 256*i;
        Ofs[idx >> 3][idx & 7] = Op[(size_t)(idx >> 3) * 32 + (idx & 7)];
    }
    if (t < 64) ((float2*)E8is)[t] = g_E8i[t];
    __syncthreads();
    int v = t >> 3, k = t & 7;
    float2 gg[8];
    #pragma unroll
    for (int m = 0; m < 8; m++) {
        float gx = 0.f, gy = 0.f;
        #pragma unroll
        for (int j = 0; j < 8; j++) {
            int sx = m + 8*j;
            float2 o  = Ofs[sx][k];
            float2 tw = g_TV[sx * 32 + v];
            gx = fmaf(o.x, tw.x, fmaf( o.y, tw.y, gx));
            gy = fmaf(o.y, tw.x, fmaf(-o.x, tw.y, gy));
        }
        gg[m] = make_float2(gx, gy);
    }
    #pragma unroll
    for (int a = 0; a < 8; a++) {
        float tx = 0.f, ty = 0.f;
        #pragma unroll
        for (int m = 0; m < 8; m++) {
            float2 e = E8is[m][a];
            tx = fmaf(gg[m].x, e.x, fmaf(-gg[m].y, e.y, tx));
            ty = fmaf(gg[m].x, e.y, fmaf( gg[m].y, e.x, ty));
        }
        g_Tmp[((size_t)bco * 256 + v + 32*a) * 32 + kq * 8 + k] = make_float2(tx, ty);
    }
}

// ============== K5: inverse real DFT along W via mma.sync; B from global frags ==============
#define IR_SMEM 36864
__global__ void __launch_bounds__(256) k_irfftW_m(float* __restrict__ out) {
    extern __shared__ unsigned char smem[];
    __nv_bfloat16* Ah = (__nv_bfloat16*)(smem);             // [128][72 pad]
    __nv_bfloat16* Al = (__nv_bfloat16*)(smem + 18432);
    int tid = threadIdx.x, lane = tid & 31, wid = tid >> 5;
    int g = lane >> 2, t4 = lane & 3;
    int rg = blockIdx.x >> 1, nh = blockIdx.x & 1;
    size_t rowBase = (size_t)rg * 128;

    // stage A: 128 rows x 64 floats from g_Tmp, split to bf16 hi/lo
    {
        const float4* ag = (const float4*)g_Tmp;
        #pragma unroll
        for (int i = 0; i < 8; i++) {
            int idx = tid + 256 * i;
            int r = idx >> 4, c4 = idx & 15;
            float4 v = ag[(rowBase + r) * 16 + c4];
            __nv_bfloat16 h0, h1, h2, h3, l0, l1, l2, l3;
            split_bf(v.x, h0, l0); split_bf(v.y, h1, l1);
            split_bf(v.z, h2, l2); split_bf(v.w, h3, l3);
            *(uint2*)(Ah + r * 72 + c4 * 4) = make_uint2(pack_bf(h0, h1), pack_bf(h2, h3));
            *(uint2*)(Al + r * 72 + c4 * 4) = make_uint2(pack_bf(l0, l1), pack_bf(l2, l3));
        }
    }
    __syncthreads();

    int m0 = (wid >> 1) * 32;
    int n0 = (wid & 1) * 64;
    float acc[2][8][4];
    #pragma unroll
    for (int mt = 0; mt < 2; mt++)
        #pragma unroll
        for (int nt = 0; nt < 8; nt++)
            #pragma unroll
            for (int i = 0; i < 4; i++) acc[mt][nt][i] = 0.f;

    #pragma unroll
    for (int ks = 0; ks < 4; ks++) {
        uint32_t ah[2][4], al[2][4];
        #pragma unroll
        for (int mt = 0; mt < 2; mt++) {
            int aoff = (m0 + mt * 16 + g) * 72 + ks * 16 + 2 * t4;
            ah[mt][0] = *(const uint32_t*)(Ah + aoff);
            ah[mt][1] = *(const uint32_t*)(Ah + aoff + 8 * 72);
            ah[mt][2] = *(const uint32_t*)(Ah + aoff + 8);
            ah[mt][3] = *(const uint32_t*)(Ah + aoff + 8 * 72 + 8);
            al[mt][0] = *(const uint32_t*)(Al + aoff);
            al[mt][1] = *(const uint32_t*)(Al + aoff + 8 * 72);
            al[mt][2] = *(const uint32_t*)(Al + aoff + 8);
            al[mt][3] = *(const uint32_t*)(Al + aoff + 8 * 72 + 8);
        }
        #pragma unroll
        for (int nt = 0; nt < 8; nt++) {
            int fi = ((nh * 16 + (n0 >> 3) + nt) * 4 + ks) * 32 + lane;
            uint2 bhv = g_IRBh[fi];
            uint2 blv = g_IRBl[fi];
            uint32_t bh[2] = {bhv.x, bhv.y};
            uint32_t bl[2] = {blv.x, blv.y};
            #pragma unroll
            for (int mt = 0; mt < 2; mt++) {
                mma16816(acc[mt][nt], ah[mt], bh);
                mma16816(acc[mt][nt], ah[mt], bl);
                mma16816(acc[mt][nt], al[mt], bh);
            }
        }
    }
    #pragma unroll
    for (int mt = 0; mt < 2; mt++) {
        size_t r0 = rowBase + m0 + mt * 16 + g;
        #pragma unroll
        for (int nt = 0; nt < 8; nt++) {
            int col = nh * 128 + n0 + nt * 8 + 2 * t4;
            *(float2*)(out + r0 * 256 + col)       = make_float2(acc[mt][nt][0], acc[mt][nt][1]);
            *(float2*)(out + (r0 + 8) * 256 + col) = make_float2(acc[mt][nt][2], acc[mt][nt][3]);
        }
    }
}

extern "C" void kernel_launch(void* const* d_in, const int* in_sizes, int n_in,
                              void* d_out, int out_size) {
    const float* x   = (const float*)d_in[0];
    const float* fs  = (const float*)d_in[1];
    const float* w0  = (const float*)d_in[2];
    const float* w1  = (const float*)d_in[3];
    const float* we0 = (const float*)d_in[4];
    const float* we1 = (const float*)d_in[5];
    float* out = (float*)d_out;

    cudaFuncSetAttribute(k_fwdW_m,   cudaFuncAttributeMaxDynamicSharedMemorySize, FW_SMEM);
    cudaFuncSetAttribute(k_irfftW_m, cudaFuncAttributeMaxDynamicSharedMemorySize, IR_SMEM);

    k_init<<<41, 256>>>();
    k_wtrans<<<4096, 256>>>(w0, w1, we0, we1);
    k_fwdW_m<<<RTOT / 128, 256, FW_SMEM>>>(x);        // 1024 CTAs
    k_fwdH<<<Bsz * CIn * 4, 256>>>();                 // 2048 CTAs
    k_mix<<<2 * 1024, 256>>>(fs);                     // 2048 CTAs
    k_invH<<<Bsz * COn * 4, 256>>>();                 // 2048 CTAs
    k_irfftW_m<<<RTOT / 64, 256, IR_SMEM>>>(out);     // 2048 CTAs
}

// round 12
// speedup vs baseline: 1.5649x; 1.2115x over previous
#include <cuda_runtime.h>
#include <cuda_bf16.h>
#include <math.h>
#include <stdint.h>

// Problem constants
#define Bsz 16
#define CIn 32
#define COn 32
#define Hn  256
#define Wn  256
#define KM  32
#define SXn 64
#define RTOT (Bsz*CIn*Hn)   // 131072 rows

// ============================ tables ============================
__device__ float2 g_TV [64*32];   // [sx][v] e^{-2pi i kx(sx) v/256}
__device__ float2 g_E8 [8*8];
__device__ float2 g_E8i[8*8];
// fwdW basis  [kc(4)][n(64)][72pad]  bf16 hi/lo (smem-staged per chunk — R6 style)
__device__ __align__(16) __nv_bfloat16 g_BWh[4*64*72], g_BWl[4*64*72];
// irfft basis [nh(2)][wn(128)][72pad] bf16 hi/lo (smem-staged — R6 style)
__device__ __align__(16) __nv_bfloat16 g_BIh[2*128*72], g_BIl[2*128*72];

// ============================ scratch ============================
__device__ float2 g_Xw[(size_t)RTOT*KM];          // fwdW out [row][k]
__device__ float2 g_Xf[(size_t)Bsz*CIn*SXn*KM];   // fwdH out [bci][sx][k]
__device__ float2 g_Of[(size_t)Bsz*COn*SXn*KM];   // mix out  [bco][sx][k]
// invH out, bf16 hi/lo planes in irfftW's A layout: [row][64] = interleaved (re,im) per ky
__device__ __align__(16) __nv_bfloat16 g_TmpAh[(size_t)Bsz*COn*Hn*64];
__device__ __align__(16) __nv_bfloat16 g_TmpAl[(size_t)Bsz*COn*Hn*64];
__device__ float2 g_Wt [2*1024*1024];
__device__ float2 g_Wet[2*1024*1024];

// ============================ helpers ============================
__device__ __forceinline__ uint32_t pack_bf(__nv_bfloat16 a, __nv_bfloat16 b) {
    return (uint32_t)__bfloat16_as_ushort(a) | ((uint32_t)__bfloat16_as_ushort(b) << 16);
}
__device__ __forceinline__ void split_bf(float v, __nv_bfloat16& h, __nv_bfloat16& l) {
    h = __float2bfloat16(v);
    l = __float2bfloat16(v - __bfloat162float(h));
}
__device__ __forceinline__ void mma16816(float* c, const uint32_t* a, const uint32_t* b) {
    asm volatile("mma.sync.aligned.m16n8k16.row.col.f32.bf16.bf16.f32 "
        "{%0,%1,%2,%3}, {%4,%5,%6,%7}, {%8,%9}, {%0,%1,%2,%3};"
        : "+f"(c[0]), "+f"(c[1]), "+f"(c[2]), "+f"(c[3])
        : "r"(a[0]), "r"(a[1]), "r"(a[2]), "r"(a[3]), "r"(b[0]), "r"(b[1]));
}

#define SEG 18432   // 4*64*72 == 2*128*72

__global__ void k_init() {
    int t = blockIdx.x * blockDim.x + threadIdx.x;
    if (t < 2048) {                     // g_TV
        int sx = t >> 5, v = t & 31;
        int kx = (sx < 32) ? sx : (192 + sx);
        float s, c; sincospif((float)(kx * v) / 128.0f, &s, &c);
        g_TV[t] = make_float2(c, -s);
    }
    int t1 = t - 2048;
    if (t1 >= 0 && t1 < 64) {           // E8 / E8i
        int m = t1 >> 3, a = t1 & 7;
        float s, c; sincospif((float)(m * a) / 4.0f, &s, &c);
        g_E8 [t1] = make_float2(c, -s);
        g_E8i[t1] = make_float2(c,  s);
    }
    int t2 = t1 - 64;
    if (t2 >= 0 && t2 < SEG) {          // fwdW basis
        int kc = t2 / (64*72);
        int rem = t2 % (64*72);
        int n = rem / 72, kk = rem % 72;
        float v = 0.f;
        if (kk < 64) {
            int w = kc * 64 + kk;
            float s, c; sincospif((float)((n >> 1) * w) / 128.0f, &s, &c);
            v = (n & 1) ? -s : c;
        }
        __nv_bfloat16 h, l; split_bf(v, h, l);
        g_BWh[t2] = h; g_BWl[t2] = l;
    }
    int t3 = t2 - SEG;
    if (t3 >= 0 && t3 < SEG) {          // irfft basis
        int nh = t3 / (128*72);
        int rem = t3 % (128*72);
        int wn = rem / 72, j = rem % 72;
        float v = 0.f;
        if (j < 64) {
            int w = nh * 128 + wn;
            int q = j >> 1;
            float s, c; sincospif((float)(q * w) / 128.0f, &s, &c);
            float alpha = ((q == 0) ? 1.0f : 2.0f) * (1.0f / 256.0f);
            v = (j & 1) ? -alpha * s : alpha * c;
        }
        __nv_bfloat16 h, l; split_bf(v, h, l);
        g_BIh[t3] = h; g_BIl[t3] = l;
    }
}

// ---- K0b: transpose weights [p][kxy] -> [kxy][p] ----
__global__ void __launch_bounds__(256) k_wtrans(const float* __restrict__ w0,
                                                const float* __restrict__ w1,
                                                const float* __restrict__ we0,
                                                const float* __restrict__ we1) {
    __shared__ float2 sm[32][33];
    int bid = blockIdx.x;
    int arr = bid >> 10;
    int tile = bid & 1023;
    int I = tile >> 5, J = tile & 31;
    const float2* src = (const float2*)((arr == 0) ? w0 : (arr == 1) ? w1 : (arr == 2) ? we0 : we1);
    float2* dst = (arr < 2) ? (g_Wt + (size_t)arr * 1024 * 1024)
                            : (g_Wet + (size_t)(arr - 2) * 1024 * 1024);
    int t = threadIdx.x;
    int c = t & 31, rq = t >> 5;
    #pragma unroll
    for (int i = 0; i < 4; i++)
        sm[rq + 8 * i][c] = src[(size_t)(I * 32 + rq + 8 * i) * 1024 + J * 32 + c];
    __syncthreads();
    #pragma unroll
    for (int i = 0; i < 4; i++)
        dst[(size_t)(J * 32 + rq + 8 * i) * 1024 + I * 32 + c] = sm[c][rq + 8 * i];
}

// ============== K1: fwd DFT along W via mma.sync (R6 verbatim) ==============
#define FW_SMEM 55296
__global__ void __launch_bounds__(256) k_fwdW_m(const float* __restrict__ x) {
    extern __shared__ unsigned char smem[];
    __nv_bfloat16* Ah = (__nv_bfloat16*)(smem);
    __nv_bfloat16* Al = (__nv_bfloat16*)(smem + 18432);
    __nv_bfloat16* Bh = (__nv_bfloat16*)(smem + 36864);
    __nv_bfloat16* Bl = (__nv_bfloat16*)(smem + 46080);
    int tid = threadIdx.x, lane = tid & 31, wid = tid >> 5;
    int g = lane >> 2, t4 = lane & 3;
    size_t rowBase = (size_t)blockIdx.x * 128;
    int m0 = wid * 16;
    float acc[8][4];
    #pragma unroll
    for (int nt = 0; nt < 8; nt++)
        #pragma unroll
        for (int i = 0; i < 4; i++) acc[nt][i] = 0.f;

    const float4* xg = (const float4*)x;
    for (int kc = 0; kc < 4; kc++) {
        __syncthreads();
        #pragma unroll
        for (int i = 0; i < 8; i++) {
            int idx = tid + 256 * i;
            int r = idx >> 4, c4 = idx & 15;
            float4 v = xg[(rowBase + r) * 64 + kc * 16 + c4];
            __nv_bfloat16 h0, h1, h2, h3, l0, l1, l2, l3;
            split_bf(v.x, h0, l0); split_bf(v.y, h1, l1);
            split_bf(v.z, h2, l2); split_bf(v.w, h3, l3);
            *(uint2*)(Ah + r * 72 + c4 * 4) = make_uint2(pack_bf(h0, h1), pack_bf(h2, h3));
            *(uint2*)(Al + r * 72 + c4 * 4) = make_uint2(pack_bf(l0, l1), pack_bf(l2, l3));
        }
        {
            const uint4* sh = ((const uint4*)g_BWh) + kc * 576;
            const uint4* sl = ((const uint4*)g_BWl) + kc * 576;
            uint4* dh = (uint4*)Bh; uint4* dl = (uint4*)Bl;
            for (int i = tid; i < 576; i += 256) { dh[i] = sh[i]; dl[i] = sl[i]; }
        }
        __syncthreads();
        #pragma unroll
        for (int ks = 0; ks < 4; ks++) {
            int aoff = (m0 + g) * 72 + ks * 16 + 2 * t4;
            uint32_t ah[4], al[4];
            ah[0] = *(const uint32_t*)(Ah + aoff);
            ah[1] = *(const uint32_t*)(Ah + aoff + 8 * 72);
            ah[2] = *(const uint32_t*)(Ah + aoff + 8);
            ah[3] = *(const uint32_t*)(Ah + aoff + 8 * 72 + 8);
            al[0] = *(const uint32_t*)(Al + aoff);
            al[1] = *(const uint32_t*)(Al + aoff + 8 * 72);
            al[2] = *(const uint32_t*)(Al + aoff + 8);
            al[3] = *(const uint32_t*)(Al + aoff + 8 * 72 + 8);
            #pragma unroll
            for (int nt = 0; nt < 8; nt++) {
                int boff = (nt * 8 + g) * 72 + ks * 16 + 2 * t4;
                uint32_t bh[2], bl[2];
                bh[0] = *(const uint32_t*)(Bh + boff);
                bh[1] = *(const uint32_t*)(Bh + boff + 8);
                bl[0] = *(const uint32_t*)(Bl + boff);
                bl[1] = *(const uint32_t*)(Bl + boff + 8);
                mma16816(acc[nt], ah, bh);
                mma16816(acc[nt], ah, bl);
                mma16816(acc[nt], al, bh);
            }
        }
    }
    float2* gx = (float2*)g_Xw;
    #pragma unroll
    for (int nt = 0; nt < 8; nt++) {
        int col = nt * 4 + t4;
        gx[(rowBase + m0 + g) * 32 + col]     = make_float2(acc[nt][0], acc[nt][1]);
        gx[(rowBase + m0 + g + 8) * 32 + col] = make_float2(acc[nt][2], acc[nt][3]);
    }
}

// ---- K2: fwd DFT along H (scalar radix-8, R6 verbatim) ----
__global__ void __launch_bounds__(256) k_fwdH() {
    __shared__ float2 Xs[256][8];
    __shared__ float2 Ys[32][8][8];
    __shared__ float2 E8s[8][8];
    int t = threadIdx.x;
    int bci = blockIdx.x >> 2, kq = blockIdx.x & 3;
    const float2* Xp = g_Xw + (size_t)bci * 256 * 32 + kq * 8;
    #pragma unroll
    for (int i = 0; i < 8; i++) {
        int idx = t + 256*i;
        Xs[idx >> 3][idx & 7] = Xp[(size_t)(idx >> 3) * 32 + (idx & 7)];
    }
    if (t < 64) ((float2*)E8s)[t] = g_E8[t];
    __syncthreads();
    int v = t >> 3, k = t & 7;
    {
        float2 xa[8];
        #pragma unroll
        for (int a = 0; a < 8; a++) xa[a] = Xs[v + 32*a][k];
        #pragma unroll
        for (int m = 0; m < 8; m++) {
            float yr = 0.f, yi = 0.f;
            #pragma unroll
            for (int a = 0; a < 8; a++) {
                float2 e = E8s[m][a];
                yr = fmaf(xa[a].x, e.x, fmaf(-xa[a].y, e.y, yr));
                yi = fmaf(xa[a].x, e.y, fmaf( xa[a].y, e.x, yi));
            }
            Ys[v][m][k] = make_float2(yr, yi);
        }
    }
    __syncthreads();
    int k2 = t & 7, sx2 = t >> 3;
    int m = sx2 & 7;
    float a0x = 0.f, a0y = 0.f, a1x = 0.f, a1y = 0.f;
    #pragma unroll 8
    for (int vv = 0; vv < 32; vv++) {
        float2 y  = Ys[vv][m][k2];
        float2 t0 = g_TV[sx2 * 32 + vv];
        float2 t1 = g_TV[(sx2 + 32) * 32 + vv];
        a0x = fmaf(y.x, t0.x, fmaf(-y.y, t0.y, a0x));
        a0y = fmaf(y.x, t0.y, fmaf( y.y, t0.x, a0y));
        a1x = fmaf(y.x, t1.x, fmaf(-y.y, t1.y, a1x));
        a1y = fmaf(y.x, t1.y, fmaf( y.y, t1.x, a1y));
    }
    const float nrm = 1.0f / 256.0f;
    g_Xf[((size_t)bci * 64 + sx2)      * 32 + kq * 8 + k2] = make_float2(a0x * nrm, a0y * nrm);
    g_Xf[((size_t)bci * 64 + sx2 + 32) * 32 + kq * 8 + k2] = make_float2(a1x * nrm, a1y * nrm);
}

// ---- K3: channel mixing (R6 verbatim) ----
__global__ void __launch_bounds__(256) k_mix(const float* __restrict__ fs) {
    __shared__ float2 Ws[1024];
    __shared__ float2 Wes[1024];
    __shared__ float2 Xs[16][32];
    __shared__ float  ssm[16];
    int bid = blockIdx.x;
    int r = bid >> 10, kxy = bid & 1023;
    int kx = kxy >> 5, ky = kxy & 31;
    int sxg = r * 32 + kx;
    const float2* Wp  = g_Wt  + ((size_t)r << 20) + ((size_t)kxy << 10);
    const float2* Wep = g_Wet + ((size_t)r << 20) + ((size_t)kxy << 10);
    int t = threadIdx.x;
    #pragma unroll
    for (int i = 0; i < 4; i++) {
        Ws [t + 256*i] = Wp [t + 256*i];
        Wes[t + 256*i] = Wep[t + 256*i];
    }
    #pragma unroll
    for (int i = 0; i < 2; i++) {
        int p = t + 256*i;
        Xs[p >> 5][p & 31] = g_Xf[((size_t)p * 64 + sxg) * 32 + ky];
    }
    if (t < 16) {
        int idx;
        if (kx < 8 && ky < 8)        idx = 0;
        else if (kx < 16 && ky < 16) idx = (kx < 8) ? 1 : ((ky < 8) ? 2 : 3);
        else                         idx = (kx < 16) ? 4 : ((ky < 16) ? 5 : 6);
        ssm[t] = fs[t * 7 + idx];
    }
    __syncthreads();
    int co = t & 31, bh = t >> 5;
    float sb0 = ssm[bh], sb1 = ssm[bh + 8];
    float a0x = 0.f, a0y = 0.f, a1x = 0.f, a1y = 0.f;
    #pragma unroll 8
    for (int ci = 0; ci < 32; ci++) {
        float2 w  = Ws [ci * 32 + co];
        float2 we = Wes[ci * 32 + co];
        float2 x0 = Xs[bh][ci];
        float2 x1 = Xs[bh + 8][ci];
        float wr0 = fmaf(sb0, we.x, w.x), wi0 = fmaf(sb0, we.y, w.y);
        float wr1 = fmaf(sb1, we.x, w.x), wi1 = fmaf(sb1, we.y, w.y);
        a0x = fmaf(x0.x, wr0, fmaf(-x0.y, wi0, a0x));
        a0y = fmaf(x0.x, wi0, fmaf( x0.y, wr0, a0y));
        a1x = fmaf(x1.x, wr1, fmaf(-x1.y, wi1, a1x));
        a1y = fmaf(x1.x, wi1, fmaf( x1.y, wr1, a1y));
    }
    g_Of[(((size_t)bh       * 32 + co) * 64 + sxg) * 32 + ky] = make_float2(a0x, a0y);
    g_Of[(((size_t)(bh + 8) * 32 + co) * 64 + sxg) * 32 + ky] = make_float2(a1x, a1y);
}

// ---- K4: inverse DFT along H (scalar radix-8); NOW EMITS bf16 hi/lo planes ----
__global__ void __launch_bounds__(256) k_invH() {
    __shared__ float2 Ofs[64][8];
    __shared__ float2 E8is[8][8];
    int t = threadIdx.x;
    int bco = blockIdx.x >> 2, kq = blockIdx.x & 3;
    const float2* Op = g_Of + (size_t)bco * 64 * 32 + kq * 8;
    #pragma unroll
    for (int i = 0; i < 2; i++) {
        int idx = t + 256*i;
        Ofs[idx >> 3][idx & 7] = Op[(size_t)(idx >> 3) * 32 + (idx & 7)];
    }
    if (t < 64) ((float2*)E8is)[t] = g_E8i[t];
    __syncthreads();
    int v = t >> 3, k = t & 7;
    float2 gg[8];
    #pragma unroll
    for (int m = 0; m < 8; m++) {
        float gx = 0.f, gy = 0.f;
        #pragma unroll
        for (int j = 0; j < 8; j++) {
            int sx = m + 8*j;
            float2 o  = Ofs[sx][k];
            float2 tw = g_TV[sx * 32 + v];
            gx = fmaf(o.x, tw.x, fmaf( o.y, tw.y, gx));
            gy = fmaf(o.y, tw.x, fmaf(-o.x, tw.y, gy));
        }
        gg[m] = make_float2(gx, gy);
    }
    int col = kq * 8 + k;
    #pragma unroll
    for (int a = 0; a < 8; a++) {
        float tx = 0.f, ty = 0.f;
        #pragma unroll
        for (int m = 0; m < 8; m++) {
            float2 e = E8is[m][a];
            tx = fmaf(gg[m].x, e.x, fmaf(-gg[m].y, e.y, tx));
            ty = fmaf(gg[m].x, e.y, fmaf( gg[m].y, e.x, ty));
        }
        // split here (same math irfftW would do) and store packed (re,im) bf16 pairs
        size_t row = (size_t)bco * 256 + v + 32 * a;
        __nv_bfloat16 hr, lr, hi, li;
        split_bf(tx, hr, lr); split_bf(ty, hi, li);
        *(uint32_t*)(g_TmpAh + row * 64 + 2 * col) = pack_bf(hr, hi);
        *(uint32_t*)(g_TmpAl + row * 64 + 2 * col) = pack_bf(lr, li);
    }
}

// ============== K5: inverse real DFT along W via mma.sync; A = pure memcpy ==============
#define IR_SMEM 73728
__global__ void __launch_bounds__(256) k_irfftW_m(float* __restrict__ out) {
    extern __shared__ unsigned char smem[];
    __nv_bfloat16* Ah = (__nv_bfloat16*)(smem);             // [128][72 pad]
    __nv_bfloat16* Al = (__nv_bfloat16*)(smem + 18432);
    __nv_bfloat16* Bh = (__nv_bfloat16*)(smem + 36864);
    __nv_bfloat16* Bl = (__nv_bfloat16*)(smem + 55296);
    int tid = threadIdx.x, lane = tid & 31, wid = tid >> 5;
    int g = lane >> 2, t4 = lane & 3;
    int rg = blockIdx.x >> 1, nh = blockIdx.x & 1;
    size_t rowBase = (size_t)rg * 128;

    // stage A: pure uint4 memcpy with pad (planes already bf16 in A layout)
    {
        const uint4* sh = (const uint4*)(g_TmpAh + rowBase * 64);
        const uint4* sl = (const uint4*)(g_TmpAl + rowBase * 64);
        #pragma unroll
        for (int i = 0; i < 4; i++) {
            int idx = tid + 256 * i;              // 1024 = 128 rows x 8 uint4
            int row = idx >> 3, c = idx & 7;
            *(uint4*)(Ah + row * 72 + c * 8) = sh[idx];
            *(uint4*)(Al + row * 72 + c * 8) = sl[idx];
        }
    }
    // stage B: constant basis half (R6 style contiguous copy)
    {
        const uint4* sh = ((const uint4*)g_BIh) + nh * 1152;
        const uint4* sl = ((const uint4*)g_BIl) + nh * 1152;
        uint4* dh = (uint4*)Bh; uint4* dl = (uint4*)Bl;
        for (int i = tid; i < 1152; i += 256) { dh[i] = sh[i]; dl[i] = sl[i]; }
    }
    __syncthreads();

    int m0 = (wid >> 1) * 32;
    int n0 = (wid & 1) * 64;
    float acc[2][8][4];
    #pragma unroll
    for (int mt = 0; mt < 2; mt++)
        #pragma unroll
        for (int nt = 0; nt < 8; nt++)
            #pragma unroll
            for (int i = 0; i < 4; i++) acc[mt][nt][i] = 0.f;

    #pragma unroll
    for (int ks = 0; ks < 4; ks++) {
        uint32_t ah[2][4], al[2][4];
        #pragma unroll
        for (int mt = 0; mt < 2; mt++) {
            int aoff = (m0 + mt * 16 + g) * 72 + ks * 16 + 2 * t4;
            ah[mt][0] = *(const uint32_t*)(Ah + aoff);
            ah[mt][1] = *(const uint32_t*)(Ah + aoff + 8 * 72);
            ah[mt][2] = *(const uint32_t*)(Ah + aoff + 8);
            ah[mt][3] = *(const uint32_t*)(Ah + aoff + 8 * 72 + 8);
            al[mt][0] = *(const uint32_t*)(Al + aoff);
            al[mt][1] = *(const uint32_t*)(Al + aoff + 8 * 72);
            al[mt][2] = *(const uint32_t*)(Al + aoff + 8);
            al[mt][3] = *(const uint32_t*)(Al + aoff + 8 * 72 + 8);
        }
        #pragma unroll
        for (int nt = 0; nt < 8; nt++) {
            int boff = (n0 + nt * 8 + g) * 72 + ks * 16 + 2 * t4;
            uint32_t bh[2], bl[2];
            bh[0] = *(const uint32_t*)(Bh + boff);
            bh[1] = *(const uint32_t*)(Bh + boff + 8);
            bl[0] = *(const uint32_t*)(Bl + boff);
            bl[1] = *(const uint32_t*)(Bl + boff + 8);
            #pragma unroll
            for (int mt = 0; mt < 2; mt++) {
                mma16816(acc[mt][nt], ah[mt], bh);
                mma16816(acc[mt][nt], ah[mt], bl);
                mma16816(acc[mt][nt], al[mt], bh);
            }
        }
    }
    #pragma unroll
    for (int mt = 0; mt < 2; mt++) {
        size_t r0 = rowBase + m0 + mt * 16 + g;
        #pragma unroll
        for (int nt = 0; nt < 8; nt++) {
            int col = nh * 128 + n0 + nt * 8 + 2 * t4;
            *(float2*)(out + r0 * 256 + col)       = make_float2(acc[mt][nt][0], acc[mt][nt][1]);
            *(float2*)(out + (r0 + 8) * 256 + col) = make_float2(acc[mt][nt][2], acc[mt][nt][3]);
        }
    }
}

extern "C" void kernel_launch(void* const* d_in, const int* in_sizes, int n_in,
                              void* d_out, int out_size) {
    const float* x   = (const float*)d_in[0];
    const float* fs  = (const float*)d_in[1];
    const float* w0  = (const float*)d_in[2];
    const float* w1  = (const float*)d_in[3];
    const float* we0 = (const float*)d_in[4];
    const float* we1 = (const float*)d_in[5];
    float* out = (float*)d_out;

    cudaFuncSetAttribute(k_fwdW_m,   cudaFuncAttributeMaxDynamicSharedMemorySize, FW_SMEM);
    cudaFuncSetAttribute(k_irfftW_m, cudaFuncAttributeMaxDynamicSharedMemorySize, IR_SMEM);

    k_init<<<153, 256>>>();
    k_wtrans<<<4096, 256>>>(w0, w1, we0, we1);
    k_fwdW_m<<<RTOT / 128, 256, FW_SMEM>>>(x);        // 1024 CTAs
    k_fwdH<<<Bsz * CIn * 4, 256>>>();                 // 2048 CTAs
    k_mix<<<2 * 1024, 256>>>(fs);                     // 2048 CTAs
    k_invH<<<Bsz * COn * 4, 256>>>();                 // 2048 CTAs
    k_irfftW_m<<<RTOT / 64, 256, IR_SMEM>>>(out);     // 2048 CTAs
}